// round 11
// baseline (speedup 1.0000x reference)
#include <cuda_runtime.h>
#include <cuda_fp16.h>
#include <math.h>
#include <stdint.h>

// Problem dims
#define NL   8
#define NB   2
#define NT   1024
#define NC   1024
#define NH   16
#define NHD  64
#define NV   50257
#define NVP  50304
#define NTOK 2048
#define C3   3072
#define C4   4096

// ---------------- scratch ----------------------------------------------------
__device__ float    g_x    [NTOK * NC];
__device__ __half   g_qkv16[NTOK * C3];
__device__ uint32_t g_h16t [NTOK * NC / 2];
__device__ uint32_t g_y16t [NTOK * NC / 2];
__device__ uint32_t g_mlp16t[NTOK * C4 / 2];
__device__ uint32_t w_attn_t[(size_t)NL * NC * C3 / 2];
__device__ uint32_t w_proj_t[(size_t)NL * NC * NC / 2];
__device__ uint32_t w_fc_t  [(size_t)NL * NC * C4 / 2];
__device__ uint32_t w_fc2_t [(size_t)NL * C4 * NC / 2];
__device__ uint32_t w_wte_t [(size_t)NVP * NC / 2];

// ---------------- helpers ----------------------------------------------------
__device__ __forceinline__ void mma_f16(float* d, const uint32_t* a, const uint32_t* b) {
    asm volatile(
        "mma.sync.aligned.m16n8k16.row.col.f32.f16.f16.f32 "
        "{%0,%1,%2,%3}, {%4,%5,%6,%7}, {%8,%9}, {%0,%1,%2,%3};"
        : "+f"(d[0]), "+f"(d[1]), "+f"(d[2]), "+f"(d[3])
        : "r"(a[0]), "r"(a[1]), "r"(a[2]), "r"(a[3]), "r"(b[0]), "r"(b[1]));
}
__device__ __forceinline__ uint32_t h2pack(float lo, float hi) {
    __half2 h = __floats2half2_rn(lo, hi);
    return *reinterpret_cast<uint32_t*>(&h);
}
__device__ __forceinline__ uint32_t smem_u32(const void* p) {
    uint32_t a;
    asm("{ .reg .u64 t; cvta.to.shared.u64 t, %1; cvt.u32.u64 %0, t; }" : "=r"(a) : "l"(p));
    return a;
}
#define CP_ASYNC16(dst, src) \
    asm volatile("cp.async.cg.shared.global [%0], [%1], 16;" :: "r"(dst), "l"(src))
#define CP_COMMIT() asm volatile("cp.async.commit_group;" ::: "memory")
#define CP_WAIT2()  asm volatile("cp.async.wait_group 2;" ::: "memory")

__device__ __forceinline__ size_t a_widx(int row, int col, int KB) {
    return ((size_t)(row >> 7) * KB + (col >> 4)) * 1024
         + ((row >> 4) & 7) * 128 + (row & 7) * 16 + ((row >> 3) & 1)
         + ((col >> 1) & 3) * 4 + ((col >> 3) & 1) * 2;
}

__device__ __forceinline__ float block_sum(float v) {
    __shared__ float sh[8];
    int lane = threadIdx.x & 31, w = threadIdx.x >> 5;
#pragma unroll
    for (int o = 16; o; o >>= 1) v += __shfl_xor_sync(0xffffffffu, v, o);
    if (lane == 0) sh[w] = v;
    __syncthreads();
    v = sh[0] + sh[1] + sh[2] + sh[3] + sh[4] + sh[5] + sh[6] + sh[7];
    __syncthreads();
    return v;
}

// ---------------- unified weight conversion (ONE launch) ----------------------
__global__ void __launch_bounds__(256) cvt_all(
    const float* __restrict__ attn_w, const float* __restrict__ proj_w,
    const float* __restrict__ fc_w,   const float* __restrict__ fc2_w,
    const float* __restrict__ wte,
    uint32_t* __restrict__ wa, uint32_t* __restrict__ wp,
    uint32_t* __restrict__ wf, uint32_t* __restrict__ wf2,
    uint32_t* __restrict__ wv)
{
    const int bid = blockIdx.x;
    const int t = threadIdx.x;
    if (bid < 49152) {
        const float* src; uint32_t* dst; int K, N, l, nt, kb;
        if (bid < 12288) {
            K = NC; N = C3; int id = bid;
            kb = id & 63; nt = (id >> 6) % 24; l = (id >> 6) / 24;
            src = attn_w; dst = wa;
        } else if (bid < 16384) {
            K = NC; N = NC; int id = bid - 12288;
            kb = id & 63; nt = (id >> 6) & 7; l = id >> 9;
            src = proj_w; dst = wp;
        } else if (bid < 32768) {
            K = NC; N = C4; int id = bid - 16384;
            kb = id & 63; nt = (id >> 6) & 31; l = id >> 11;
            src = fc_w; dst = wf;
        } else {
            K = C4; N = NC; int id = bid - 32768;
            kb = id & 255; nt = (id >> 8) & 7; l = id >> 11;
            src = fc2_w; dst = wf2;
        }
        const float* s = src + (size_t)l * K * N;
        uint32_t* d = dst + (((size_t)l * (N >> 7) + nt) * (K >> 4) + kb) * 1024;
#pragma unroll
        for (int w = 0; w < 4; w++) {
            int wid = t + 256 * w;
            int jj = wid >> 7, n = wid & 127;
            int k = kb * 16 + 2 * jj;
            int gn = nt * 128 + n;
            float lo = s[(size_t)k * N + gn];
            float hi = s[(size_t)(k + 1) * N + gn];
            d[(n >> 3) * 64 + (n & 7) * 8 + (jj & 3) * 2 + (jj >> 2)] = h2pack(lo, hi);
        }
    } else {
        int id = bid - 49152;
        int kb = id & 63, nt = id >> 6;
        uint32_t* d = wv + ((size_t)nt * 64 + kb) * 1024;
#pragma unroll
        for (int w = 0; w < 4; w++) {
            int wid = t + 256 * w;
            int nr = wid >> 3, jj = wid & 7;
            int gn = nt * 128 + nr;
            int k = kb * 16 + 2 * jj;
            float lo = 0.f, hi = 0.f;
            if (gn < NV) {
                lo = wte[(size_t)gn * NC + k];
                hi = wte[(size_t)gn * NC + k + 1];
            }
            d[(nr >> 3) * 64 + (nr & 7) * 8 + (jj & 3) * 2 + (jj >> 2)] = h2pack(lo, hi);
        }
    }
}

// ---------------- embedding / layernorm --------------------------------------
__global__ void embed_kernel(const int* __restrict__ ids,
                             const float* __restrict__ wte,
                             const float* __restrict__ wpe,
                             float* __restrict__ x) {
    int tok = blockIdx.x, t = tok & (NT - 1), id = ids[tok];
    const float* src = wte + (size_t)id * NC;
    const float* pp  = wpe + (size_t)t * NC;
    float* dst = x + (size_t)tok * NC;
    for (int c = threadIdx.x; c < NC; c += blockDim.x) dst[c] = src[c] + pp[c];
}

__global__ void __launch_bounds__(256) ln_kernel(const float* __restrict__ x,
                                                 const float* __restrict__ w,
                                                 const float* __restrict__ b,
                                                 uint32_t* __restrict__ o) {
    int row = blockIdx.x, tid = threadIdx.x;
    const float2* xr = reinterpret_cast<const float2*>(x + (size_t)row * NC);
    float2 v[2]; float s = 0.f;
#pragma unroll
    for (int i = 0; i < 2; i++) { v[i] = xr[tid + 256 * i]; s += v[i].x + v[i].y; }
    s = block_sum(s);
    float mean = s * (1.f / NC), s2 = 0.f;
#pragma unroll
    for (int i = 0; i < 2; i++) {
        float dx = v[i].x - mean, dy = v[i].y - mean;
        s2 += dx * dx + dy * dy;
    }
    s2 = block_sum(s2);
    float rstd = rsqrtf(s2 * (1.f / NC) + 1e-5f);
#pragma unroll
    for (int i = 0; i < 2; i++) {
        int col = 2 * (tid + 256 * i);
        float a0 = (v[i].x - mean) * rstd * w[col] + b[col];
        float a1 = (v[i].y - mean) * rstd * w[col + 1] + b[col + 1];
        o[a_widx(row, col, 64)] = h2pack(a0, a1);
    }
}

// =============================================================================
// 64x128-tile fragment-tiled GEMM, cp.async 4-stage (12KB/stage = 48KB).
// 8 warps, warp tile 32x32. ~70 regs -> 3 CTAs/SM.
// EPI: 1 fp32 residual add (+bias)   2 GELU -> tiled fp16 (+bias)
//      3 fp16 row-major (+bias)      4 fp32 store, no bias, col<N guard
// =============================================================================
template <int EPI>
__global__ void __launch_bounds__(256, 3) ht64(const uint32_t* __restrict__ At,
                                               const uint32_t* __restrict__ Bt,
                                               const float* __restrict__ bias,
                                               void* __restrict__ Dv,
                                               int N, int KB) {
    extern __shared__ uint32_t dsm[];
    const int tid = threadIdx.x, lane = tid & 31, warp = tid >> 5;
    const int wm = warp >> 2, wn = warp & 3;
    const int bx = blockIdx.x, by = blockIdx.y;
    const uint32_t sb = smem_u32(dsm);

    const uint32_t* Asrc = At + (size_t)(by >> 1) * KB * 1024 + (by & 1) * 512;
    const uint32_t* Bsrc = Bt + (size_t)bx * KB * 1024;
    const int KT = KB >> 1;

    const int aks = tid >> 7;
    const int aw  = (tid & 127) * 4;

    auto issue = [&](int st, int kt2) {
        uint32_t d = sb + st * 12288;
        const uint32_t* sa = Asrc + (size_t)(kt2 * 2 + aks) * 1024 + aw;
        CP_ASYNC16(d + tid * 16, sa);
        const uint32_t* sbp = Bsrc + (size_t)kt2 * 2048 + tid * 4;
        CP_ASYNC16(d + 4096 + tid * 16, sbp);
        CP_ASYNC16(d + 8192 + tid * 16, sbp + 1024);
    };

    for (int p = 0; p < 3; p++) { if (p < KT) issue(p, p); CP_COMMIT(); }

    float acc[2][4][4];
#pragma unroll
    for (int i = 0; i < 2; i++)
#pragma unroll
        for (int j = 0; j < 4; j++)
#pragma unroll
            for (int r = 0; r < 4; r++) acc[i][j][r] = 0.f;

    for (int kt = 0; kt < KT; kt++) {
        const int st = kt & 3;
        CP_WAIT2();
        __syncthreads();
        if (kt + 3 < KT) issue((kt + 3) & 3, kt + 3);
        CP_COMMIT();
#pragma unroll
        for (int s2 = 0; s2 < 2; s2++) {
            const uint32_t* As = dsm + st * 3072 + s2 * 512;
            const uint32_t* Bs = dsm + st * 3072 + 1024 + s2 * 1024;
            uint32_t af[2][4], bf[4][2];
#pragma unroll
            for (int mt = 0; mt < 2; mt++)
                *reinterpret_cast<uint4*>(af[mt]) =
                    *reinterpret_cast<const uint4*>(&As[(wm * 2 + mt) * 128 + lane * 4]);
#pragma unroll
            for (int nt = 0; nt < 4; nt++)
                *reinterpret_cast<uint2*>(bf[nt]) =
                    *reinterpret_cast<const uint2*>(&Bs[(wn * 4 + nt) * 64 + lane * 2]);
#pragma unroll
            for (int mt = 0; mt < 2; mt++)
#pragma unroll
                for (int nt = 0; nt < 4; nt++)
                    mma_f16(acc[mt][nt], af[mt], bf[nt]);
        }
    }

#pragma unroll
    for (int mt = 0; mt < 2; mt++) {
        const int row0 = by * 64 + wm * 32 + mt * 16 + (lane >> 2);
#pragma unroll
        for (int nt = 0; nt < 4; nt++) {
            const int col0 = bx * 128 + wn * 32 + nt * 8 + (lane & 3) * 2;
#pragma unroll
            for (int hf = 0; hf < 2; hf++) {
                const int row = row0 + hf * 8;
                float v0 = acc[mt][nt][hf * 2 + 0];
                float v1 = acc[mt][nt][hf * 2 + 1];
                if (EPI != 4) { v0 += bias[col0]; v1 += bias[col0 + 1]; }
                if (EPI == 1) {
                    float* drow = (float*)Dv + (size_t)row * N + col0;
                    drow[0] += v0; drow[1] += v1;
                } else if (EPI == 2) {
                    v0 = 0.5f * v0 * (1.f + erff(v0 * 0.70710678118654752f));
                    v1 = 0.5f * v1 * (1.f + erff(v1 * 0.70710678118654752f));
                    ((uint32_t*)Dv)[a_widx(row, col0, N >> 4)] = h2pack(v0, v1);
                } else if (EPI == 3) {
                    __half* drow = (__half*)Dv + (size_t)row * N + col0;
                    *reinterpret_cast<__half2*>(drow) = __floats2half2_rn(v0, v1);
                } else {
                    float* drow = (float*)Dv + (size_t)row * N;
                    if (col0 < N)     drow[col0]     = v0;
                    if (col0 + 1 < N) drow[col0 + 1] = v1;
                }
            }
        }
    }
}

// =============================================================================
// 64x64-tile GEMM (EPI1 residual+bias) for small-N GEMMs (proj, fc2).
// 8KB/stage, 4 stages = 32KB. ~50 regs -> 4+ CTAs/SM. Warp tile 32x16.
// =============================================================================
__global__ void __launch_bounds__(256, 4) hgemm_n64(const uint32_t* __restrict__ At,
                                                    const uint32_t* __restrict__ Bt,
                                                    const float* __restrict__ bias,
                                                    float* __restrict__ D,
                                                    int N, int KB) {
    extern __shared__ uint32_t dsm[];
    const int tid = threadIdx.x, lane = tid & 31, warp = tid >> 5;
    const int wm = warp >> 2, wn = warp & 3;
    const int bx = blockIdx.x, by = blockIdx.y;
    const uint32_t sb = smem_u32(dsm);

    const uint32_t* Asrc = At + (size_t)(by >> 1) * KB * 1024 + (by & 1) * 512;
    const uint32_t* Bsrc = Bt + (size_t)(bx >> 1) * KB * 1024 + (bx & 1) * 512;
    const int KT = KB >> 1;

    const int ks2 = tid >> 7;            // which k16 this thread's copies serve
    const int cw  = (tid & 127) * 4;     // word offset within 512-word half-block

    auto issue = [&](int st, int kt2) {
        uint32_t d = sb + st * 8192;
        const uint32_t* sa = Asrc + (size_t)(kt2 * 2 + ks2) * 1024 + cw;
        const uint32_t* sbp = Bsrc + (size_t)(kt2 * 2 + ks2) * 1024 + cw;
        CP_ASYNC16(d + tid * 16, sa);              // A: stage words [0,1024)
        CP_ASYNC16(d + 4096 + tid * 16, sbp);      // B: stage words [1024,2048)
    };

    for (int p = 0; p < 3; p++) { if (p < KT) issue(p, p); CP_COMMIT(); }

    float acc[2][2][4];
#pragma unroll
    for (int i = 0; i < 2; i++)
#pragma unroll
        for (int j = 0; j < 2; j++)
#pragma unroll
            for (int r = 0; r < 4; r++) acc[i][j][r] = 0.f;

    for (int kt = 0; kt < KT; kt++) {
        const int st = kt & 3;
        CP_WAIT2();
        __syncthreads();
        if (kt + 3 < KT) issue((kt + 3) & 3, kt + 3);
        CP_COMMIT();
#pragma unroll
        for (int s2 = 0; s2 < 2; s2++) {
            const uint32_t* As = dsm + st * 2048 + s2 * 512;
            const uint32_t* Bs = dsm + st * 2048 + 1024 + s2 * 512;
            uint32_t af[2][4], bf[2][2];
#pragma unroll
            for (int mt = 0; mt < 2; mt++)
                *reinterpret_cast<uint4*>(af[mt]) =
                    *reinterpret_cast<const uint4*>(&As[(wm * 2 + mt) * 128 + lane * 4]);
#pragma unroll
            for (int nt = 0; nt < 2; nt++)
                *reinterpret_cast<uint2*>(bf[nt]) =
                    *reinterpret_cast<const uint2*>(&Bs[(wn * 2 + nt) * 64 + lane * 2]);
#pragma unroll
            for (int mt = 0; mt < 2; mt++)
#pragma unroll
                for (int nt = 0; nt < 2; nt++)
                    mma_f16(acc[mt][nt], af[mt], bf[nt]);
        }
    }

#pragma unroll
    for (int mt = 0; mt < 2; mt++) {
        const int row0 = by * 64 + wm * 32 + mt * 16 + (lane >> 2);
#pragma unroll
        for (int nt = 0; nt < 2; nt++) {
            const int col0 = bx * 64 + wn * 16 + nt * 8 + (lane & 3) * 2;
#pragma unroll
            for (int hf = 0; hf < 2; hf++) {
                const int row = row0 + hf * 8;
                float* drow = D + (size_t)row * N + col0;
                drow[0] += acc[mt][nt][hf * 2 + 0] + bias[col0];
                drow[1] += acc[mt][nt][hf * 2 + 1] + bias[col0 + 1];
            }
        }
    }
}

// =============================================================================
// Flash attention (fp16 MMA, fp32 softmax/accum) — unchanged.
// =============================================================================
__global__ void __launch_bounds__(256) flash_attn(const __half* __restrict__ qkv,
                                                  uint32_t* __restrict__ yt) {
    __shared__ uint32_t sK[2][2048];
    __shared__ uint32_t sV[2][2048];
    uint32_t* sq = &sK[0][0];

    const int tid = threadIdx.x, lane = tid & 31, warp = tid >> 5;
    const int qt = blockIdx.x;
    const int bh = blockIdx.y, b = bh >> 4, h = bh & 15;

    const __half* qbase = qkv + (size_t)(b * NT + qt * 128) * C3 + h * NHD;
    const __half* kbase = qkv + (size_t)(b * NT) * C3 + NC + h * NHD;
    const __half* vbase = qkv + (size_t)(b * NT) * C3 + 2 * NC + h * NHD;

    uint32_t af[4][4];
    {
        const int r = tid >> 1, hfq = tid & 1;
        const __half* qp = qbase + (size_t)r * C3 + hfq * 32;
        uint4 v0 = *reinterpret_cast<const uint4*>(qp);
        uint4 v1 = *reinterpret_cast<const uint4*>(qp + 8);
        uint4 v2 = *reinterpret_cast<const uint4*>(qp + 16);
        uint4 v3 = *reinterpret_cast<const uint4*>(qp + 24);
        const int ab0 = (2 * hfq) * 1024 + (r >> 4) * 128 + (r & 7) * 16 + ((r >> 3) & 1);
        const int ab1 = ab0 + 1024;
        const uint32_t* w0 = reinterpret_cast<const uint32_t*>(&v0);
        const uint32_t* w1 = reinterpret_cast<const uint32_t*>(&v1);
        const uint32_t* w2 = reinterpret_cast<const uint32_t*>(&v2);
        const uint32_t* w3 = reinterpret_cast<const uint32_t*>(&v3);
#pragma unroll
        for (int i = 0; i < 4; i++) {
            sq[ab0 + i * 4]     = w0[i];
            sq[ab0 + i * 4 + 2] = w1[i];
            sq[ab1 + i * 4]     = w2[i];
            sq[ab1 + i * 4 + 2] = w3[i];
        }
        __syncthreads();
#pragma unroll
        for (int ks = 0; ks < 4; ks++)
            *reinterpret_cast<uint4*>(af[ks]) =
                *reinterpret_cast<const uint4*>(&sq[ks * 1024 + warp * 128 + lane * 4]);
        __syncthreads();
    }

    const int knr = tid >> 2, kq = tid & 3;
    const int kb  = kq * 512 + (knr >> 3) * 64 + (knr & 7) * 8;
    const int vpp = tid >> 3, vn0 = (tid & 7) * 8;
    const int vks = vpp >> 3, vjj = vpp & 7;
    int vst[4];
#pragma unroll
    for (int i = 0; i < 4; i++) {
        int n = vn0 + 2 * i;
        vst[i] = vks * 512 + (n >> 3) * 64 + ((n & 7) * 4 + (vjj & 3)) * 2 + (vjj >> 2);
    }

    float oacc[8][4];
#pragma unroll
    for (int nt = 0; nt < 8; nt++)
#pragma unroll
        for (int i = 0; i < 4; i++) oacc[nt][i] = 0.f;
    float mrun0 = -1e30f, mrun1 = -1e30f, lrun0 = 0.f, lrun1 = 0.f;

    uint4 ku0, ku1, va, vb;
    {
        const __half* kp = kbase + (size_t)knr * C3 + kq * 16;
        ku0 = *reinterpret_cast<const uint4*>(kp);
        ku1 = *reinterpret_cast<const uint4*>(kp + 8);
        const __half* vp = vbase + (size_t)(2 * vpp) * C3 + vn0;
        va = *reinterpret_cast<const uint4*>(vp);
        vb = *reinterpret_cast<const uint4*>(vp + C3);
        const uint32_t* kw0 = reinterpret_cast<const uint32_t*>(&ku0);
        const uint32_t* kw1 = reinterpret_cast<const uint32_t*>(&ku1);
        const uint32_t* vwa = reinterpret_cast<const uint32_t*>(&va);
        const uint32_t* vwb = reinterpret_cast<const uint32_t*>(&vb);
#pragma unroll
        for (int i = 0; i < 4; i++) {
            sK[0][kb + i * 2]     = kw0[i];
            sK[0][kb + i * 2 + 1] = kw1[i];
            sV[0][vst[i]]     = __byte_perm(vwa[i], vwb[i], 0x5410);
            sV[0][vst[i] + 8] = __byte_perm(vwa[i], vwb[i], 0x7632);
        }
    }
    __syncthreads();

    for (int kt = 0; kt < 16; kt++) {
        const int s = kt & 1;
        if (kt + 1 < 16) {
            const __half* kp = kbase + (size_t)((kt + 1) * 64 + knr) * C3 + kq * 16;
            ku0 = *reinterpret_cast<const uint4*>(kp);
            ku1 = *reinterpret_cast<const uint4*>(kp + 8);
            const __half* vp = vbase + (size_t)((kt + 1) * 64 + 2 * vpp) * C3 + vn0;
            va = *reinterpret_cast<const uint4*>(vp);
            vb = *reinterpret_cast<const uint4*>(vp + C3);
        }

        float sacc[8][4];
#pragma unroll
        for (int nt = 0; nt < 8; nt++) {
#pragma unroll
            for (int i = 0; i < 4; i++) sacc[nt][i] = 0.f;
#pragma unroll
            for (int ks = 0; ks < 4; ks++) {
                uint32_t bfr[2];
                *reinterpret_cast<uint2*>(bfr) =
                    *reinterpret_cast<const uint2*>(&sK[s][ks * 512 + nt * 64 + lane * 2]);
                mma_f16(sacc[nt], af[ks], bfr);
            }
        }

        float m0 = -1e30f, m1 = -1e30f;
#pragma unroll
        for (int nt = 0; nt < 8; nt++) {
#pragma unroll
            for (int i = 0; i < 4; i++) sacc[nt][i] *= 0.125f;
            m0 = fmaxf(m0, fmaxf(sacc[nt][0], sacc[nt][1]));
            m1 = fmaxf(m1, fmaxf(sacc[nt][2], sacc[nt][3]));
        }
        m0 = fmaxf(m0, __shfl_xor_sync(0xffffffffu, m0, 1));
        m0 = fmaxf(m0, __shfl_xor_sync(0xffffffffu, m0, 2));
        m1 = fmaxf(m1, __shfl_xor_sync(0xffffffffu, m1, 1));
        m1 = fmaxf(m1, __shfl_xor_sync(0xffffffffu, m1, 2));
        const float mn0 = fmaxf(mrun0, m0), mn1 = fmaxf(mrun1, m1);
        const float al0 = __expf(mrun0 - mn0), al1 = __expf(mrun1 - mn1);
        mrun0 = mn0; mrun1 = mn1;

        float r0 = 0.f, r1 = 0.f;
#pragma unroll
        for (int nt = 0; nt < 8; nt++) {
            sacc[nt][0] = __expf(sacc[nt][0] - mn0);
            sacc[nt][1] = __expf(sacc[nt][1] - mn0);
            sacc[nt][2] = __expf(sacc[nt][2] - mn1);
            sacc[nt][3] = __expf(sacc[nt][3] - mn1);
            r0 += sacc[nt][0] + sacc[nt][1];
            r1 += sacc[nt][2] + sacc[nt][3];
        }
        r0 += __shfl_xor_sync(0xffffffffu, r0, 1);
        r0 += __shfl_xor_sync(0xffffffffu, r0, 2);
        r1 += __shfl_xor_sync(0xffffffffu, r1, 1);
        r1 += __shfl_xor_sync(0xffffffffu, r1, 2);
        lrun0 = lrun0 * al0 + r0;
        lrun1 = lrun1 * al1 + r1;

#pragma unroll
        for (int nt = 0; nt < 8; nt++) {
            oacc[nt][0] *= al0; oacc[nt][1] *= al0;
            oacc[nt][2] *= al1; oacc[nt][3] *= al1;
        }

        uint32_t pf[4][4];
#pragma unroll
        for (int ks = 0; ks < 4; ks++) {
            pf[ks][0] = h2pack(sacc[2 * ks][0],     sacc[2 * ks][1]);
            pf[ks][1] = h2pack(sacc[2 * ks][2],     sacc[2 * ks][3]);
            pf[ks][2] = h2pack(sacc[2 * ks + 1][0], sacc[2 * ks + 1][1]);
            pf[ks][3] = h2pack(sacc[2 * ks + 1][2], sacc[2 * ks + 1][3]);
        }
#pragma unroll
        for (int nt = 0; nt < 8; nt++) {
#pragma unroll
            for (int ks = 0; ks < 4; ks++) {
                uint32_t bfr[2];
                *reinterpret_cast<uint2*>(bfr) =
                    *reinterpret_cast<const uint2*>(&sV[s][ks * 512 + nt * 64 + lane * 2]);
                mma_f16(oacc[nt], pf[ks], bfr);
            }
        }

        if (kt + 1 < 16) {
            const int ns = s ^ 1;
            const uint32_t* kw0 = reinterpret_cast<const uint32_t*>(&ku0);
            const uint32_t* kw1 = reinterpret_cast<const uint32_t*>(&ku1);
            const uint32_t* vwa = reinterpret_cast<const uint32_t*>(&va);
            const uint32_t* vwb = reinterpret_cast<const uint32_t*>(&vb);
#pragma unroll
            for (int i = 0; i < 4; i++) {
                sK[ns][kb + i * 2]     = kw0[i];
                sK[ns][kb + i * 2 + 1] = kw1[i];
                sV[ns][vst[i]]     = __byte_perm(vwa[i], vwb[i], 0x5410);
                sV[ns][vst[i] + 8] = __byte_perm(vwa[i], vwb[i], 0x7632);
            }
        }
        __syncthreads();
    }

    const float inv0 = 1.f / lrun0, inv1 = 1.f / lrun1;
    const int rowA = b * NT + qt * 128 + warp * 16 + (lane >> 2);
    const int colb = h * NHD + (lane & 3) * 2;
#pragma unroll
    for (int nt = 0; nt < 8; nt++) {
        yt[a_widx(rowA,     colb + nt * 8, 64)] =
            h2pack(oacc[nt][0] * inv0, oacc[nt][1] * inv0);
        yt[a_widx(rowA + 8, colb + nt * 8, 64)] =
            h2pack(oacc[nt][2] * inv1, oacc[nt][3] * inv1);
    }
}

// ---------------- host orchestration -----------------------------------------
#define SMEM_T64 49152
#define SMEM_N64 32768

extern "C" void kernel_launch(void* const* d_in, const int* in_sizes, int n_in,
                              void* d_out, int out_size) {
    const int*   ids    = (const int*)  d_in[0];
    const float* wte    = (const float*)d_in[1];
    const float* wpe    = (const float*)d_in[2];
    const float* ln1_w  = (const float*)d_in[3];
    const float* ln1_b  = (const float*)d_in[4];
    const float* attn_w = (const float*)d_in[5];
    const float* attn_b = (const float*)d_in[6];
    const float* proj_w = (const float*)d_in[7];
    const float* proj_b = (const float*)d_in[8];
    const float* ln2_w  = (const float*)d_in[9];
    const float* ln2_b  = (const float*)d_in[10];
    const float* fc_w   = (const float*)d_in[11];
    const float* fc_b   = (const float*)d_in[12];
    const float* fc2_w  = (const float*)d_in[13];
    const float* fc2_b  = (const float*)d_in[14];
    const float* lnf_w  = (const float*)d_in[15];
    const float* lnf_b  = (const float*)d_in[16];
    float* out = (float*)d_out;

    float* x;
    __half* qkv16;
    uint32_t *h16t, *y16t, *mlp16t, *wa, *wp, *wf, *wf2, *wv;
    cudaGetSymbolAddress((void**)&x,      g_x);
    cudaGetSymbolAddress((void**)&qkv16,  g_qkv16);
    cudaGetSymbolAddress((void**)&h16t,   g_h16t);
    cudaGetSymbolAddress((void**)&y16t,   g_y16t);
    cudaGetSymbolAddress((void**)&mlp16t, g_mlp16t);
    cudaGetSymbolAddress((void**)&wa,     w_attn_t);
    cudaGetSymbolAddress((void**)&wp,     w_proj_t);
    cudaGetSymbolAddress((void**)&wf,     w_fc_t);
    cudaGetSymbolAddress((void**)&wf2,    w_fc2_t);
    cudaGetSymbolAddress((void**)&wv,     w_wte_t);

    cudaFuncSetAttribute(ht64<1>, cudaFuncAttributeMaxDynamicSharedMemorySize, SMEM_T64);
    cudaFuncSetAttribute(ht64<2>, cudaFuncAttributeMaxDynamicSharedMemorySize, SMEM_T64);
    cudaFuncSetAttribute(ht64<3>, cudaFuncAttributeMaxDynamicSharedMemorySize, SMEM_T64);
    cudaFuncSetAttribute(ht64<4>, cudaFuncAttributeMaxDynamicSharedMemorySize, SMEM_T64);
    cudaFuncSetAttribute(hgemm_n64, cudaFuncAttributeMaxDynamicSharedMemorySize, SMEM_N64);

    embed_kernel<<<NTOK, 256>>>(ids, wte, wpe, x);
    cvt_all<<<74304, 256>>>(attn_w, proj_w, fc_w, fc2_w, wte, wa, wp, wf, wf2, wv);

    const size_t wa_s = (size_t)NC * C3 / 2, wp_s = (size_t)NC * NC / 2;
    const size_t wf_s = (size_t)NC * C4 / 2, wf2_s = (size_t)C4 * NC / 2;

    for (int l = 0; l < NL; l++) {
        ln_kernel<<<NTOK, 256>>>(x, ln1_w + (size_t)l * NC, ln1_b + (size_t)l * NC, h16t);
        ht64<3><<<dim3(C3 / 128, NTOK / 64), 256, SMEM_T64>>>(
            h16t, wa + l * wa_s, attn_b + (size_t)l * C3, qkv16, C3, 64);
        flash_attn<<<dim3(NT / 128, NB * NH), 256>>>(qkv16, y16t);
        hgemm_n64<<<dim3(NC / 64, NTOK / 64), 256, SMEM_N64>>>(
            y16t, wp + l * wp_s, proj_b + (size_t)l * NC, x, NC, 64);
        ln_kernel<<<NTOK, 256>>>(x, ln2_w + (size_t)l * NC, ln2_b + (size_t)l * NC, h16t);
        ht64<2><<<dim3(C4 / 128, NTOK / 64), 256, SMEM_T64>>>(
            h16t, wf + l * wf_s, fc_b + (size_t)l * C4, mlp16t, C4, 64);
        hgemm_n64<<<dim3(NC / 64, NTOK / 64), 256, SMEM_N64>>>(
            mlp16t, wf2 + l * wf2_s, fc2_b + (size_t)l * NC, x, NC, 256);
    }

    ln_kernel<<<NTOK, 256>>>(x, lnf_w, lnf_b, h16t);
    ht64<4><<<dim3(NVP / 128, NTOK / 64), 256, SMEM_T64>>>(
        h16t, wv, nullptr, out, NV, 64);
}

// round 12
// speedup vs baseline: 1.0481x; 1.0481x over previous
#include <cuda_runtime.h>
#include <cuda_fp16.h>
#include <math.h>
#include <stdint.h>

// Problem dims
#define NL   8
#define NB   2
#define NT   1024
#define NC   1024
#define NH   16
#define NHD  64
#define NV   50257
#define NVP  50304
#define NTOK 2048
#define C3   3072
#define C4   4096

// ---------------- scratch ----------------------------------------------------
__device__ float    g_x    [NTOK * NC];
__device__ __half   g_qkv16[NTOK * C3];
__device__ uint32_t g_h16t [NTOK * NC / 2];
__device__ uint32_t g_y16t [NTOK * NC / 2];
__device__ uint32_t g_mlp16t[NTOK * C4 / 2];
__device__ uint32_t w_attn_t[(size_t)NL * NC * C3 / 2];
__device__ uint32_t w_proj_t[(size_t)NL * NC * NC / 2];
__device__ uint32_t w_fc_t  [(size_t)NL * NC * C4 / 2];
__device__ uint32_t w_fc2_t [(size_t)NL * C4 * NC / 2];
__device__ uint32_t w_wte_t [(size_t)NVP * NC / 2];

// ---------------- helpers ----------------------------------------------------
__device__ __forceinline__ void mma_f16(float* d, const uint32_t* a, const uint32_t* b) {
    asm volatile(
        "mma.sync.aligned.m16n8k16.row.col.f32.f16.f16.f32 "
        "{%0,%1,%2,%3}, {%4,%5,%6,%7}, {%8,%9}, {%0,%1,%2,%3};"
        : "+f"(d[0]), "+f"(d[1]), "+f"(d[2]), "+f"(d[3])
        : "r"(a[0]), "r"(a[1]), "r"(a[2]), "r"(a[3]), "r"(b[0]), "r"(b[1]));
}
__device__ __forceinline__ uint32_t h2pack(float lo, float hi) {
    __half2 h = __floats2half2_rn(lo, hi);
    return *reinterpret_cast<uint32_t*>(&h);
}
__device__ __forceinline__ uint32_t smem_u32(const void* p) {
    uint32_t a;
    asm("{ .reg .u64 t; cvta.to.shared.u64 t, %1; cvt.u32.u64 %0, t; }" : "=r"(a) : "l"(p));
    return a;
}
#define CP_ASYNC16(dst, src) \
    asm volatile("cp.async.cg.shared.global [%0], [%1], 16;" :: "r"(dst), "l"(src))
#define CP_COMMIT() asm volatile("cp.async.commit_group;" ::: "memory")
#define CP_WAIT2()  asm volatile("cp.async.wait_group 2;" ::: "memory")

__device__ __forceinline__ size_t a_widx(int row, int col, int KB) {
    return ((size_t)(row >> 7) * KB + (col >> 4)) * 1024
         + ((row >> 4) & 7) * 128 + (row & 7) * 16 + ((row >> 3) & 1)
         + ((col >> 1) & 3) * 4 + ((col >> 3) & 1) * 2;
}

__device__ __forceinline__ float block_sum(float v) {
    __shared__ float sh[8];
    int lane = threadIdx.x & 31, w = threadIdx.x >> 5;
#pragma unroll
    for (int o = 16; o; o >>= 1) v += __shfl_xor_sync(0xffffffffu, v, o);
    if (lane == 0) sh[w] = v;
    __syncthreads();
    v = sh[0] + sh[1] + sh[2] + sh[3] + sh[4] + sh[5] + sh[6] + sh[7];
    __syncthreads();
    return v;
}

// ---------------- unified weight conversion (ONE launch) ----------------------
__global__ void __launch_bounds__(256) cvt_all(
    const float* __restrict__ attn_w, const float* __restrict__ proj_w,
    const float* __restrict__ fc_w,   const float* __restrict__ fc2_w,
    const float* __restrict__ wte,
    uint32_t* __restrict__ wa, uint32_t* __restrict__ wp,
    uint32_t* __restrict__ wf, uint32_t* __restrict__ wf2,
    uint32_t* __restrict__ wv)
{
    const int bid = blockIdx.x;
    const int t = threadIdx.x;
    if (bid < 49152) {
        const float* src; uint32_t* dst; int K, N, l, nt, kb;
        if (bid < 12288) {
            K = NC; N = C3; int id = bid;
            kb = id & 63; nt = (id >> 6) % 24; l = (id >> 6) / 24;
            src = attn_w; dst = wa;
        } else if (bid < 16384) {
            K = NC; N = NC; int id = bid - 12288;
            kb = id & 63; nt = (id >> 6) & 7; l = id >> 9;
            src = proj_w; dst = wp;
        } else if (bid < 32768) {
            K = NC; N = C4; int id = bid - 16384;
            kb = id & 63; nt = (id >> 6) & 31; l = id >> 11;
            src = fc_w; dst = wf;
        } else {
            K = C4; N = NC; int id = bid - 32768;
            kb = id & 255; nt = (id >> 8) & 7; l = id >> 11;
            src = fc2_w; dst = wf2;
        }
        const float* s = src + (size_t)l * K * N;
        uint32_t* d = dst + (((size_t)l * (N >> 7) + nt) * (K >> 4) + kb) * 1024;
#pragma unroll
        for (int w = 0; w < 4; w++) {
            int wid = t + 256 * w;
            int jj = wid >> 7, n = wid & 127;
            int k = kb * 16 + 2 * jj;
            int gn = nt * 128 + n;
            float lo = s[(size_t)k * N + gn];
            float hi = s[(size_t)(k + 1) * N + gn];
            d[(n >> 3) * 64 + (n & 7) * 8 + (jj & 3) * 2 + (jj >> 2)] = h2pack(lo, hi);
        }
    } else {
        int id = bid - 49152;
        int kb = id & 63, nt = id >> 6;
        uint32_t* d = wv + ((size_t)nt * 64 + kb) * 1024;
#pragma unroll
        for (int w = 0; w < 4; w++) {
            int wid = t + 256 * w;
            int nr = wid >> 3, jj = wid & 7;
            int gn = nt * 128 + nr;
            int k = kb * 16 + 2 * jj;
            float lo = 0.f, hi = 0.f;
            if (gn < NV) {
                lo = wte[(size_t)gn * NC + k];
                hi = wte[(size_t)gn * NC + k + 1];
            }
            d[(nr >> 3) * 64 + (nr & 7) * 8 + (jj & 3) * 2 + (jj >> 2)] = h2pack(lo, hi);
        }
    }
}

// ---------------- embedding / layernorm --------------------------------------
__global__ void embed_kernel(const int* __restrict__ ids,
                             const float* __restrict__ wte,
                             const float* __restrict__ wpe,
                             float* __restrict__ x) {
    int tok = blockIdx.x, t = tok & (NT - 1), id = ids[tok];
    const float* src = wte + (size_t)id * NC;
    const float* pp  = wpe + (size_t)t * NC;
    float* dst = x + (size_t)tok * NC;
    for (int c = threadIdx.x; c < NC; c += blockDim.x) dst[c] = src[c] + pp[c];
}

__global__ void __launch_bounds__(256) ln_kernel(const float* __restrict__ x,
                                                 const float* __restrict__ w,
                                                 const float* __restrict__ b,
                                                 uint32_t* __restrict__ o) {
    int row = blockIdx.x, tid = threadIdx.x;
    const float2* xr = reinterpret_cast<const float2*>(x + (size_t)row * NC);
    float2 v[2]; float s = 0.f;
#pragma unroll
    for (int i = 0; i < 2; i++) { v[i] = xr[tid + 256 * i]; s += v[i].x + v[i].y; }
    s = block_sum(s);
    float mean = s * (1.f / NC), s2 = 0.f;
#pragma unroll
    for (int i = 0; i < 2; i++) {
        float dx = v[i].x - mean, dy = v[i].y - mean;
        s2 += dx * dx + dy * dy;
    }
    s2 = block_sum(s2);
    float rstd = rsqrtf(s2 * (1.f / NC) + 1e-5f);
#pragma unroll
    for (int i = 0; i < 2; i++) {
        int col = 2 * (tid + 256 * i);
        float a0 = (v[i].x - mean) * rstd * w[col] + b[col];
        float a1 = (v[i].y - mean) * rstd * w[col + 1] + b[col + 1];
        o[a_widx(row, col, 64)] = h2pack(a0, a1);
    }
}

// =============================================================================
// 128x128-tile GEMM, 128 threads (4 warps, 2x2), warp tile 64x64.
// Per k16/warp: 32 HMMA on 4 A-frag + 8 B-frag loads (halved LDS per FLOP).
// cp.async 4-stage (16KB/stage = 64KB). Same smem image as before.
// EPI: 1 fp32 residual add (+bias)   2 GELU -> tiled fp16 (+bias)
//      3 fp16 row-major (+bias)      4 fp32 store, no bias, col<N guard
// =============================================================================
template <int EPI>
__global__ void __launch_bounds__(128) hgemm_w(const uint32_t* __restrict__ At,
                                               const uint32_t* __restrict__ Bt,
                                               const float* __restrict__ bias,
                                               void* __restrict__ Dv,
                                               int N, int KB) {
    extern __shared__ uint32_t dsm[];
    const int tid = threadIdx.x, lane = tid & 31, warp = tid >> 5;
    const int wm = warp >> 1, wn = warp & 1;
    const int bx = blockIdx.x, by = blockIdx.y;
    const uint32_t sb = smem_u32(dsm);

    const uint32_t* Asrc = At + (size_t)by * KB * 1024;
    const uint32_t* Bsrc = Bt + (size_t)bx * KB * 1024;
    const int KT = KB >> 1;

    auto issue = [&](int st, int kt2) {
        uint32_t d = sb + st * 16384 + tid * 16;
        const uint32_t* sa = Asrc + (size_t)kt2 * 2048 + tid * 4;
        const uint32_t* sbp = Bsrc + (size_t)kt2 * 2048 + tid * 4;
#pragma unroll
        for (int c = 0; c < 4; c++) {
            CP_ASYNC16(d + c * 2048,        sa  + c * 512);
            CP_ASYNC16(d + 8192 + c * 2048, sbp + c * 512);
        }
    };

    for (int p = 0; p < 3; p++) { if (p < KT) issue(p, p); CP_COMMIT(); }

    float acc[4][8][4];
#pragma unroll
    for (int i = 0; i < 4; i++)
#pragma unroll
        for (int j = 0; j < 8; j++)
#pragma unroll
            for (int r = 0; r < 4; r++) acc[i][j][r] = 0.f;

    for (int kt = 0; kt < KT; kt++) {
        const int st = kt & 3;
        CP_WAIT2();
        __syncthreads();
        if (kt + 3 < KT) issue((kt + 3) & 3, kt + 3);
        CP_COMMIT();
#pragma unroll
        for (int s2 = 0; s2 < 2; s2++) {
            const uint32_t* As = dsm + st * 4096 + s2 * 1024;
            const uint32_t* Bs = dsm + st * 4096 + 2048 + s2 * 1024;
            uint32_t af[4][4], bf[8][2];
#pragma unroll
            for (int mt = 0; mt < 4; mt++)
                *reinterpret_cast<uint4*>(af[mt]) =
                    *reinterpret_cast<const uint4*>(&As[(wm * 4 + mt) * 128 + lane * 4]);
#pragma unroll
            for (int nt = 0; nt < 8; nt++)
                *reinterpret_cast<uint2*>(bf[nt]) =
                    *reinterpret_cast<const uint2*>(&Bs[(wn * 8 + nt) * 64 + lane * 2]);
#pragma unroll
            for (int mt = 0; mt < 4; mt++)
#pragma unroll
                for (int nt = 0; nt < 8; nt++)
                    mma_f16(acc[mt][nt], af[mt], bf[nt]);
        }
    }

#pragma unroll
    for (int mt = 0; mt < 4; mt++) {
        const int row0 = by * 128 + wm * 64 + mt * 16 + (lane >> 2);
#pragma unroll
        for (int nt = 0; nt < 8; nt++) {
            const int col0 = bx * 128 + wn * 64 + nt * 8 + (lane & 3) * 2;
#pragma unroll
            for (int hf = 0; hf < 2; hf++) {
                const int row = row0 + hf * 8;
                float v0 = acc[mt][nt][hf * 2 + 0];
                float v1 = acc[mt][nt][hf * 2 + 1];
                if (EPI != 4) { v0 += bias[col0]; v1 += bias[col0 + 1]; }
                if (EPI == 1) {
                    float* drow = (float*)Dv + (size_t)row * N + col0;
                    drow[0] += v0; drow[1] += v1;
                } else if (EPI == 2) {
                    v0 = 0.5f * v0 * (1.f + erff(v0 * 0.70710678118654752f));
                    v1 = 0.5f * v1 * (1.f + erff(v1 * 0.70710678118654752f));
                    ((uint32_t*)Dv)[a_widx(row, col0, N >> 4)] = h2pack(v0, v1);
                } else if (EPI == 3) {
                    __half* drow = (__half*)Dv + (size_t)row * N + col0;
                    *reinterpret_cast<__half2*>(drow) = __floats2half2_rn(v0, v1);
                } else {
                    float* drow = (float*)Dv + (size_t)row * N;
                    if (col0 < N)     drow[col0]     = v0;
                    if (col0 + 1 < N) drow[col0 + 1] = v1;
                }
            }
        }
    }
}

// =============================================================================
// 64x128-tile GEMM (EPI1 residual+bias) for proj/fc2 (R10-validated).
// 8 warps, warp tile 32x32, 12KB/stage = 48KB.
// =============================================================================
__global__ void __launch_bounds__(256) hgemm_t64(const uint32_t* __restrict__ At,
                                                 const uint32_t* __restrict__ Bt,
                                                 const float* __restrict__ bias,
                                                 float* __restrict__ D,
                                                 int N, int KB) {
    extern __shared__ uint32_t dsm[];
    const int tid = threadIdx.x, lane = tid & 31, warp = tid >> 5;
    const int wm = warp >> 2, wn = warp & 3;
    const int bx = blockIdx.x, by = blockIdx.y;
    const uint32_t sb = smem_u32(dsm);

    const uint32_t* Asrc = At + (size_t)(by >> 1) * KB * 1024 + (by & 1) * 512;
    const uint32_t* Bsrc = Bt + (size_t)bx * KB * 1024;
    const int KT = KB >> 1;

    const int aks = tid >> 7;
    const int aw  = (tid & 127) * 4;

    auto issue = [&](int st, int kt2) {
        uint32_t d = sb + st * 12288;
        const uint32_t* sa = Asrc + (size_t)(kt2 * 2 + aks) * 1024 + aw;
        CP_ASYNC16(d + tid * 16, sa);
        const uint32_t* sbp = Bsrc + (size_t)kt2 * 2048 + tid * 4;
        CP_ASYNC16(d + 4096 + tid * 16, sbp);
        CP_ASYNC16(d + 8192 + tid * 16, sbp + 1024);
    };

    for (int p = 0; p < 3; p++) { if (p < KT) issue(p, p); CP_COMMIT(); }

    float acc[2][4][4];
#pragma unroll
    for (int i = 0; i < 2; i++)
#pragma unroll
        for (int j = 0; j < 4; j++)
#pragma unroll
            for (int r = 0; r < 4; r++) acc[i][j][r] = 0.f;

    for (int kt = 0; kt < KT; kt++) {
        const int st = kt & 3;
        CP_WAIT2();
        __syncthreads();
        if (kt + 3 < KT) issue((kt + 3) & 3, kt + 3);
        CP_COMMIT();
#pragma unroll
        for (int s2 = 0; s2 < 2; s2++) {
            const uint32_t* As = dsm + st * 3072 + s2 * 512;
            const uint32_t* Bs = dsm + st * 3072 + 1024 + s2 * 1024;
            uint32_t af[2][4], bf[4][2];
#pragma unroll
            for (int mt = 0; mt < 2; mt++)
                *reinterpret_cast<uint4*>(af[mt]) =
                    *reinterpret_cast<const uint4*>(&As[(wm * 2 + mt) * 128 + lane * 4]);
#pragma unroll
            for (int nt = 0; nt < 4; nt++)
                *reinterpret_cast<uint2*>(bf[nt]) =
                    *reinterpret_cast<const uint2*>(&Bs[(wn * 4 + nt) * 64 + lane * 2]);
#pragma unroll
            for (int mt = 0; mt < 2; mt++)
#pragma unroll
                for (int nt = 0; nt < 4; nt++)
                    mma_f16(acc[mt][nt], af[mt], bf[nt]);
        }
    }

#pragma unroll
    for (int mt = 0; mt < 2; mt++) {
        const int row0 = by * 64 + wm * 32 + mt * 16 + (lane >> 2);
#pragma unroll
        for (int nt = 0; nt < 4; nt++) {
            const int col0 = bx * 128 + wn * 32 + nt * 8 + (lane & 3) * 2;
#pragma unroll
            for (int hf = 0; hf < 2; hf++) {
                const int row = row0 + hf * 8;
                float* drow = D + (size_t)row * N + col0;
                drow[0] += acc[mt][nt][hf * 2 + 0] + bias[col0];
                drow[1] += acc[mt][nt][hf * 2 + 1] + bias[col0 + 1];
            }
        }
    }
}

// =============================================================================
// Flash attention (fp16 MMA, fp32 softmax/accum) — unchanged.
// =============================================================================
__global__ void __launch_bounds__(256) flash_attn(const __half* __restrict__ qkv,
                                                  uint32_t* __restrict__ yt) {
    __shared__ uint32_t sK[2][2048];
    __shared__ uint32_t sV[2][2048];
    uint32_t* sq = &sK[0][0];

    const int tid = threadIdx.x, lane = tid & 31, warp = tid >> 5;
    const int qt = blockIdx.x;
    const int bh = blockIdx.y, b = bh >> 4, h = bh & 15;

    const __half* qbase = qkv + (size_t)(b * NT + qt * 128) * C3 + h * NHD;
    const __half* kbase = qkv + (size_t)(b * NT) * C3 + NC + h * NHD;
    const __half* vbase = qkv + (size_t)(b * NT) * C3 + 2 * NC + h * NHD;

    uint32_t af[4][4];
    {
        const int r = tid >> 1, hfq = tid & 1;
        const __half* qp = qbase + (size_t)r * C3 + hfq * 32;
        uint4 v0 = *reinterpret_cast<const uint4*>(qp);
        uint4 v1 = *reinterpret_cast<const uint4*>(qp + 8);
        uint4 v2 = *reinterpret_cast<const uint4*>(qp + 16);
        uint4 v3 = *reinterpret_cast<const uint4*>(qp + 24);
        const int ab0 = (2 * hfq) * 1024 + (r >> 4) * 128 + (r & 7) * 16 + ((r >> 3) & 1);
        const int ab1 = ab0 + 1024;
        const uint32_t* w0 = reinterpret_cast<const uint32_t*>(&v0);
        const uint32_t* w1 = reinterpret_cast<const uint32_t*>(&v1);
        const uint32_t* w2 = reinterpret_cast<const uint32_t*>(&v2);
        const uint32_t* w3 = reinterpret_cast<const uint32_t*>(&v3);
#pragma unroll
        for (int i = 0; i < 4; i++) {
            sq[ab0 + i * 4]     = w0[i];
            sq[ab0 + i * 4 + 2] = w1[i];
            sq[ab1 + i * 4]     = w2[i];
            sq[ab1 + i * 4 + 2] = w3[i];
        }
        __syncthreads();
#pragma unroll
        for (int ks = 0; ks < 4; ks++)
            *reinterpret_cast<uint4*>(af[ks]) =
                *reinterpret_cast<const uint4*>(&sq[ks * 1024 + warp * 128 + lane * 4]);
        __syncthreads();
    }

    const int knr = tid >> 2, kq = tid & 3;
    const int kb  = kq * 512 + (knr >> 3) * 64 + (knr & 7) * 8;
    const int vpp = tid >> 3, vn0 = (tid & 7) * 8;
    const int vks = vpp >> 3, vjj = vpp & 7;
    int vst[4];
#pragma unroll
    for (int i = 0; i < 4; i++) {
        int n = vn0 + 2 * i;
        vst[i] = vks * 512 + (n >> 3) * 64 + ((n & 7) * 4 + (vjj & 3)) * 2 + (vjj >> 2);
    }

    float oacc[8][4];
#pragma unroll
    for (int nt = 0; nt < 8; nt++)
#pragma unroll
        for (int i = 0; i < 4; i++) oacc[nt][i] = 0.f;
    float mrun0 = -1e30f, mrun1 = -1e30f, lrun0 = 0.f, lrun1 = 0.f;

    uint4 ku0, ku1, va, vb;
    {
        const __half* kp = kbase + (size_t)knr * C3 + kq * 16;
        ku0 = *reinterpret_cast<const uint4*>(kp);
        ku1 = *reinterpret_cast<const uint4*>(kp + 8);
        const __half* vp = vbase + (size_t)(2 * vpp) * C3 + vn0;
        va = *reinterpret_cast<const uint4*>(vp);
        vb = *reinterpret_cast<const uint4*>(vp + C3);
        const uint32_t* kw0 = reinterpret_cast<const uint32_t*>(&ku0);
        const uint32_t* kw1 = reinterpret_cast<const uint32_t*>(&ku1);
        const uint32_t* vwa = reinterpret_cast<const uint32_t*>(&va);
        const uint32_t* vwb = reinterpret_cast<const uint32_t*>(&vb);
#pragma unroll
        for (int i = 0; i < 4; i++) {
            sK[0][kb + i * 2]     = kw0[i];
            sK[0][kb + i * 2 + 1] = kw1[i];
            sV[0][vst[i]]     = __byte_perm(vwa[i], vwb[i], 0x5410);
            sV[0][vst[i] + 8] = __byte_perm(vwa[i], vwb[i], 0x7632);
        }
    }
    __syncthreads();

    for (int kt = 0; kt < 16; kt++) {
        const int s = kt & 1;
        if (kt + 1 < 16) {
            const __half* kp = kbase + (size_t)((kt + 1) * 64 + knr) * C3 + kq * 16;
            ku0 = *reinterpret_cast<const uint4*>(kp);
            ku1 = *reinterpret_cast<const uint4*>(kp + 8);
            const __half* vp = vbase + (size_t)((kt + 1) * 64 + 2 * vpp) * C3 + vn0;
            va = *reinterpret_cast<const uint4*>(vp);
            vb = *reinterpret_cast<const uint4*>(vp + C3);
        }

        float sacc[8][4];
#pragma unroll
        for (int nt = 0; nt < 8; nt++) {
#pragma unroll
            for (int i = 0; i < 4; i++) sacc[nt][i] = 0.f;
#pragma unroll
            for (int ks = 0; ks < 4; ks++) {
                uint32_t bfr[2];
                *reinterpret_cast<uint2*>(bfr) =
                    *reinterpret_cast<const uint2*>(&sK[s][ks * 512 + nt * 64 + lane * 2]);
                mma_f16(sacc[nt], af[ks], bfr);
            }
        }

        float m0 = -1e30f, m1 = -1e30f;
#pragma unroll
        for (int nt = 0; nt < 8; nt++) {
#pragma unroll
            for (int i = 0; i < 4; i++) sacc[nt][i] *= 0.125f;
            m0 = fmaxf(m0, fmaxf(sacc[nt][0], sacc[nt][1]));
            m1 = fmaxf(m1, fmaxf(sacc[nt][2], sacc[nt][3]));
        }
        m0 = fmaxf(m0, __shfl_xor_sync(0xffffffffu, m0, 1));
        m0 = fmaxf(m0, __shfl_xor_sync(0xffffffffu, m0, 2));
        m1 = fmaxf(m1, __shfl_xor_sync(0xffffffffu, m1, 1));
        m1 = fmaxf(m1, __shfl_xor_sync(0xffffffffu, m1, 2));
        const float mn0 = fmaxf(mrun0, m0), mn1 = fmaxf(mrun1, m1);
        const float al0 = __expf(mrun0 - mn0), al1 = __expf(mrun1 - mn1);
        mrun0 = mn0; mrun1 = mn1;

        float r0 = 0.f, r1 = 0.f;
#pragma unroll
        for (int nt = 0; nt < 8; nt++) {
            sacc[nt][0] = __expf(sacc[nt][0] - mn0);
            sacc[nt][1] = __expf(sacc[nt][1] - mn0);
            sacc[nt][2] = __expf(sacc[nt][2] - mn1);
            sacc[nt][3] = __expf(sacc[nt][3] - mn1);
            r0 += sacc[nt][0] + sacc[nt][1];
            r1 += sacc[nt][2] + sacc[nt][3];
        }
        r0 += __shfl_xor_sync(0xffffffffu, r0, 1);
        r0 += __shfl_xor_sync(0xffffffffu, r0, 2);
        r1 += __shfl_xor_sync(0xffffffffu, r1, 1);
        r1 += __shfl_xor_sync(0xffffffffu, r1, 2);
        lrun0 = lrun0 * al0 + r0;
        lrun1 = lrun1 * al1 + r1;

#pragma unroll
        for (int nt = 0; nt < 8; nt++) {
            oacc[nt][0] *= al0; oacc[nt][1] *= al0;
            oacc[nt][2] *= al1; oacc[nt][3] *= al1;
        }

        uint32_t pf[4][4];
#pragma unroll
        for (int ks = 0; ks < 4; ks++) {
            pf[ks][0] = h2pack(sacc[2 * ks][0],     sacc[2 * ks][1]);
            pf[ks][1] = h2pack(sacc[2 * ks][2],     sacc[2 * ks][3]);
            pf[ks][2] = h2pack(sacc[2 * ks + 1][0], sacc[2 * ks + 1][1]);
            pf[ks][3] = h2pack(sacc[2 * ks + 1][2], sacc[2 * ks + 1][3]);
        }
#pragma unroll
        for (int nt = 0; nt < 8; nt++) {
#pragma unroll
            for (int ks = 0; ks < 4; ks++) {
                uint32_t bfr[2];
                *reinterpret_cast<uint2*>(bfr) =
                    *reinterpret_cast<const uint2*>(&sV[s][ks * 512 + nt * 64 + lane * 2]);
                mma_f16(oacc[nt], pf[ks], bfr);
            }
        }

        if (kt + 1 < 16) {
            const int ns = s ^ 1;
            const uint32_t* kw0 = reinterpret_cast<const uint32_t*>(&ku0);
            const uint32_t* kw1 = reinterpret_cast<const uint32_t*>(&ku1);
            const uint32_t* vwa = reinterpret_cast<const uint32_t*>(&va);
            const uint32_t* vwb = reinterpret_cast<const uint32_t*>(&vb);
#pragma unroll
            for (int i = 0; i < 4; i++) {
                sK[ns][kb + i * 2]     = kw0[i];
                sK[ns][kb + i * 2 + 1] = kw1[i];
                sV[ns][vst[i]]     = __byte_perm(vwa[i], vwb[i], 0x5410);
                sV[ns][vst[i] + 8] = __byte_perm(vwa[i], vwb[i], 0x7632);
            }
        }
        __syncthreads();
    }

    const float inv0 = 1.f / lrun0, inv1 = 1.f / lrun1;
    const int rowA = b * NT + qt * 128 + warp * 16 + (lane >> 2);
    const int colb = h * NHD + (lane & 3) * 2;
#pragma unroll
    for (int nt = 0; nt < 8; nt++) {
        yt[a_widx(rowA,     colb + nt * 8, 64)] =
            h2pack(oacc[nt][0] * inv0, oacc[nt][1] * inv0);
        yt[a_widx(rowA + 8, colb + nt * 8, 64)] =
            h2pack(oacc[nt][2] * inv1, oacc[nt][3] * inv1);
    }
}

// ---------------- host orchestration -----------------------------------------
#define SMEM_W   65536
#define SMEM_T64 49152

extern "C" void kernel_launch(void* const* d_in, const int* in_sizes, int n_in,
                              void* d_out, int out_size) {
    const int*   ids    = (const int*)  d_in[0];
    const float* wte    = (const float*)d_in[1];
    const float* wpe    = (const float*)d_in[2];
    const float* ln1_w  = (const float*)d_in[3];
    const float* ln1_b  = (const float*)d_in[4];
    const float* attn_w = (const float*)d_in[5];
    const float* attn_b = (const float*)d_in[6];
    const float* proj_w = (const float*)d_in[7];
    const float* proj_b = (const float*)d_in[8];
    const float* ln2_w  = (const float*)d_in[9];
    const float* ln2_b  = (const float*)d_in[10];
    const float* fc_w   = (const float*)d_in[11];
    const float* fc_b   = (const float*)d_in[12];
    const float* fc2_w  = (const float*)d_in[13];
    const float* fc2_b  = (const float*)d_in[14];
    const float* lnf_w  = (const float*)d_in[15];
    const float* lnf_b  = (const float*)d_in[16];
    float* out = (float*)d_out;

    float* x;
    __half* qkv16;
    uint32_t *h16t, *y16t, *mlp16t, *wa, *wp, *wf, *wf2, *wv;
    cudaGetSymbolAddress((void**)&x,      g_x);
    cudaGetSymbolAddress((void**)&qkv16,  g_qkv16);
    cudaGetSymbolAddress((void**)&h16t,   g_h16t);
    cudaGetSymbolAddress((void**)&y16t,   g_y16t);
    cudaGetSymbolAddress((void**)&mlp16t, g_mlp16t);
    cudaGetSymbolAddress((void**)&wa,     w_attn_t);
    cudaGetSymbolAddress((void**)&wp,     w_proj_t);
    cudaGetSymbolAddress((void**)&wf,     w_fc_t);
    cudaGetSymbolAddress((void**)&wf2,    w_fc2_t);
    cudaGetSymbolAddress((void**)&wv,     w_wte_t);

    cudaFuncSetAttribute(hgemm_w<1>, cudaFuncAttributeMaxDynamicSharedMemorySize, SMEM_W);
    cudaFuncSetAttribute(hgemm_w<2>, cudaFuncAttributeMaxDynamicSharedMemorySize, SMEM_W);
    cudaFuncSetAttribute(hgemm_w<3>, cudaFuncAttributeMaxDynamicSharedMemorySize, SMEM_W);
    cudaFuncSetAttribute(hgemm_w<4>, cudaFuncAttributeMaxDynamicSharedMemorySize, SMEM_W);
    cudaFuncSetAttribute(hgemm_t64,  cudaFuncAttributeMaxDynamicSharedMemorySize, SMEM_T64);

    embed_kernel<<<NTOK, 256>>>(ids, wte, wpe, x);
    cvt_all<<<74304, 256>>>(attn_w, proj_w, fc_w, fc2_w, wte, wa, wp, wf, wf2, wv);

    const size_t wa_s = (size_t)NC * C3 / 2, wp_s = (size_t)NC * NC / 2;
    const size_t wf_s = (size_t)NC * C4 / 2, wf2_s = (size_t)C4 * NC / 2;

    for (int l = 0; l < NL; l++) {
        ln_kernel<<<NTOK, 256>>>(x, ln1_w + (size_t)l * NC, ln1_b + (size_t)l * NC, h16t);
        hgemm_w<3><<<dim3(C3 / 128, NTOK / 128), 128, SMEM_W>>>(
            h16t, wa + l * wa_s, attn_b + (size_t)l * C3, qkv16, C3, 64);
        flash_attn<<<dim3(NT / 128, NB * NH), 256>>>(qkv16, y16t);
        hgemm_t64<<<dim3(NC / 128, NTOK / 64), 256, SMEM_T64>>>(
            y16t, wp + l * wp_s, proj_b + (size_t)l * NC, x, NC, 64);
        ln_kernel<<<NTOK, 256>>>(x, ln2_w + (size_t)l * NC, ln2_b + (size_t)l * NC, h16t);
        hgemm_w<2><<<dim3(C4 / 128, NTOK / 128), 128, SMEM_W>>>(
            h16t, wf + l * wf_s, fc_b + (size_t)l * C4, mlp16t, C4, 64);
        hgemm_t64<<<dim3(NC / 128, NTOK / 64), 256, SMEM_T64>>>(
            mlp16t, wf2 + l * wf2_s, fc2_b + (size_t)l * NC, x, NC, 256);
    }

    ln_kernel<<<NTOK, 256>>>(x, lnf_w, lnf_b, h16t);
    hgemm_w<4><<<dim3(NVP / 128, NTOK / 128), 128, SMEM_W>>>(
        h16t, wv, nullptr, out, NV, 64);
}

// round 13
// speedup vs baseline: 1.0584x; 1.0098x over previous
#include <cuda_runtime.h>
#include <cuda_fp16.h>
#include <math.h>
#include <stdint.h>

// Problem dims
#define NL   8
#define NB   2
#define NT   1024
#define NC   1024
#define NH   16
#define NHD  64
#define NV   50257
#define NVP  50304
#define NTOK 2048
#define C3   3072
#define C4   4096

// ---------------- scratch ----------------------------------------------------
__device__ float    g_x    [NTOK * NC];
__device__ __half   g_qkv16[NTOK * C3];
__device__ uint32_t g_h16t [NTOK * NC / 2];
__device__ uint32_t g_y16t [NTOK * NC / 2];
__device__ uint32_t g_mlp16t[NTOK * C4 / 2];
__device__ uint32_t w_attn_t[(size_t)NL * NC * C3 / 2];
__device__ uint32_t w_proj_t[(size_t)NL * NC * NC / 2];
__device__ uint32_t w_fc_t  [(size_t)NL * NC * C4 / 2];
__device__ uint32_t w_fc2_t [(size_t)NL * C4 * NC / 2];
__device__ uint32_t w_wte_t [(size_t)NVP * NC / 2];

// ---------------- helpers ----------------------------------------------------
__device__ __forceinline__ void mma_f16(float* d, const uint32_t* a, const uint32_t* b) {
    asm volatile(
        "mma.sync.aligned.m16n8k16.row.col.f32.f16.f16.f32 "
        "{%0,%1,%2,%3}, {%4,%5,%6,%7}, {%8,%9}, {%0,%1,%2,%3};"
        : "+f"(d[0]), "+f"(d[1]), "+f"(d[2]), "+f"(d[3])
        : "r"(a[0]), "r"(a[1]), "r"(a[2]), "r"(a[3]), "r"(b[0]), "r"(b[1]));
}
__device__ __forceinline__ uint32_t h2pack(float lo, float hi) {
    __half2 h = __floats2half2_rn(lo, hi);
    return *reinterpret_cast<uint32_t*>(&h);
}
__device__ __forceinline__ uint32_t smem_u32(const void* p) {
    uint32_t a;
    asm("{ .reg .u64 t; cvta.to.shared.u64 t, %1; cvt.u32.u64 %0, t; }" : "=r"(a) : "l"(p));
    return a;
}
#define CP_ASYNC16(dst, src) \
    asm volatile("cp.async.cg.shared.global [%0], [%1], 16;" :: "r"(dst), "l"(src))
#define CP_COMMIT() asm volatile("cp.async.commit_group;" ::: "memory")
#define CP_WAIT2()  asm volatile("cp.async.wait_group 2;" ::: "memory")

__device__ __forceinline__ size_t a_widx(int row, int col, int KB) {
    return ((size_t)(row >> 7) * KB + (col >> 4)) * 1024
         + ((row >> 4) & 7) * 128 + (row & 7) * 16 + ((row >> 3) & 1)
         + ((col >> 1) & 3) * 4 + ((col >> 3) & 1) * 2;
}

__device__ __forceinline__ float block_sum(float v) {
    __shared__ float sh[8];
    int lane = threadIdx.x & 31, w = threadIdx.x >> 5;
#pragma unroll
    for (int o = 16; o; o >>= 1) v += __shfl_xor_sync(0xffffffffu, v, o);
    if (lane == 0) sh[w] = v;
    __syncthreads();
    v = sh[0] + sh[1] + sh[2] + sh[3] + sh[4] + sh[5] + sh[6] + sh[7];
    __syncthreads();
    return v;
}

// ---------------- unified weight conversion (ONE launch, smem-staged) ---------
// segments: attn 12288 | proj 4096 | fc 16384 | fc2 16384 | wte 25152 = 74304
// All gmem writes are contiguous 4KB bursts (256 x uint4 from smem).
__global__ void __launch_bounds__(256) cvt_all(
    const float* __restrict__ attn_w, const float* __restrict__ proj_w,
    const float* __restrict__ fc_w,   const float* __restrict__ fc2_w,
    const float* __restrict__ wte,
    uint32_t* __restrict__ wa, uint32_t* __restrict__ wp,
    uint32_t* __restrict__ wf, uint32_t* __restrict__ wf2,
    uint32_t* __restrict__ wv)
{
    __shared__ float    sf[2048];   // 16x128 (NN) or 128x16 (wte) fp32 tile
    __shared__ uint32_t so[1024];   // fragment-ordered output tile
    const int bid = blockIdx.x;
    const int t = threadIdx.x;

    uint32_t* dout;
    if (bid < 49152) {  // NN tensors: in[k][n] -> [l][ntile][kblock][1024]
        const float* src; uint32_t* dst; int K, N, l, nt, kb;
        if (bid < 12288) {
            K = NC; N = C3; int id = bid;
            kb = id & 63; nt = (id >> 6) % 24; l = (id >> 6) / 24;
            src = attn_w; dst = wa;
        } else if (bid < 16384) {
            K = NC; N = NC; int id = bid - 12288;
            kb = id & 63; nt = (id >> 6) & 7; l = id >> 9;
            src = proj_w; dst = wp;
        } else if (bid < 32768) {
            K = NC; N = C4; int id = bid - 16384;
            kb = id & 63; nt = (id >> 6) & 31; l = id >> 11;
            src = fc_w; dst = wf;
        } else {
            K = C4; N = NC; int id = bid - 32768;
            kb = id & 255; nt = (id >> 8) & 7; l = id >> 11;
            src = fc2_w; dst = wf2;
        }
        const float* s = src + (size_t)l * K * N;
        dout = dst + (((size_t)l * (N >> 7) + nt) * (K >> 4) + kb) * 1024;

        // coalesced load: 16 rows x 512B
        float4* sf4 = reinterpret_cast<float4*>(sf);
#pragma unroll
        for (int i = 0; i < 2; i++) {
            int idx = t + 256 * i;              // 0..511
            int row = idx >> 5, c4 = idx & 31;
            sf4[row * 32 + c4] = *reinterpret_cast<const float4*>(
                s + (size_t)(kb * 16 + row) * N + nt * 128 + c4 * 4);
        }
        __syncthreads();
        // pack into fragment order in smem
#pragma unroll
        for (int w = 0; w < 4; w++) {
            int wid = t + 256 * w;
            int jj = wid >> 7, n = wid & 127;
            so[(n >> 3) * 64 + (n & 7) * 8 + (jj & 3) * 2 + (jj >> 2)] =
                h2pack(sf[2 * jj * 128 + n], sf[(2 * jj + 1) * 128 + n]);
        }
    } else {            // wte NT: in[n][k] -> [ntile][kblock][1024], zero-padded
        int id = bid - 49152;
        int kb = id & 63, nt = id >> 6;
        dout = wv + ((size_t)nt * 64 + kb) * 1024;

        // coalesced load: 128 rows x 64B (zero-pad rows >= NV)
        float4* sf4 = reinterpret_cast<float4*>(sf);
#pragma unroll
        for (int i = 0; i < 2; i++) {
            int idx = t + 256 * i;              // 0..511
            int nr = idx >> 2, k4 = idx & 3;
            int gn = nt * 128 + nr;
            float4 v = make_float4(0.f, 0.f, 0.f, 0.f);
            if (gn < NV)
                v = *reinterpret_cast<const float4*>(
                    wte + (size_t)gn * NC + kb * 16 + k4 * 4);
            sf4[nr * 4 + k4] = v;
        }
        __syncthreads();
#pragma unroll
        for (int w = 0; w < 4; w++) {
            int wid = t + 256 * w;
            int nr = wid >> 3, jj = wid & 7;
            so[(nr >> 3) * 64 + (nr & 7) * 8 + (jj & 3) * 2 + (jj >> 2)] =
                h2pack(sf[nr * 16 + 2 * jj], sf[nr * 16 + 2 * jj + 1]);
        }
    }
    __syncthreads();
    // contiguous 4KB burst write
    reinterpret_cast<uint4*>(dout)[t] = reinterpret_cast<const uint4*>(so)[t];
}

// ---------------- embedding / layernorm --------------------------------------
__global__ void embed_kernel(const int* __restrict__ ids,
                             const float* __restrict__ wte,
                             const float* __restrict__ wpe,
                             float* __restrict__ x) {
    int tok = blockIdx.x, t = tok & (NT - 1), id = ids[tok];
    const float* src = wte + (size_t)id * NC;
    const float* pp  = wpe + (size_t)t * NC;
    float* dst = x + (size_t)tok * NC;
    for (int c = threadIdx.x; c < NC; c += blockDim.x) dst[c] = src[c] + pp[c];
}

__global__ void __launch_bounds__(256) ln_kernel(const float* __restrict__ x,
                                                 const float* __restrict__ w,
                                                 const float* __restrict__ b,
                                                 uint32_t* __restrict__ o) {
    int row = blockIdx.x, tid = threadIdx.x;
    const float2* xr = reinterpret_cast<const float2*>(x + (size_t)row * NC);
    float2 v[2]; float s = 0.f;
#pragma unroll
    for (int i = 0; i < 2; i++) { v[i] = xr[tid + 256 * i]; s += v[i].x + v[i].y; }
    s = block_sum(s);
    float mean = s * (1.f / NC), s2 = 0.f;
#pragma unroll
    for (int i = 0; i < 2; i++) {
        float dx = v[i].x - mean, dy = v[i].y - mean;
        s2 += dx * dx + dy * dy;
    }
    s2 = block_sum(s2);
    float rstd = rsqrtf(s2 * (1.f / NC) + 1e-5f);
#pragma unroll
    for (int i = 0; i < 2; i++) {
        int col = 2 * (tid + 256 * i);
        float a0 = (v[i].x - mean) * rstd * w[col] + b[col];
        float a1 = (v[i].y - mean) * rstd * w[col + 1] + b[col + 1];
        o[a_widx(row, col, 64)] = h2pack(a0, a1);
    }
}

// =============================================================================
// 128x128-tile GEMM, 128 threads (4 warps, 2x2), warp tile 64x64.
// cp.async 4-stage (16KB/stage = 64KB).
// EPI: 1 fp32 residual add (+bias)   2 GELU -> tiled fp16 (+bias)
//      3 fp16 row-major (+bias)      4 fp32 store, no bias, col<N guard
// =============================================================================
template <int EPI>
__global__ void __launch_bounds__(128) hgemm_w(const uint32_t* __restrict__ At,
                                               const uint32_t* __restrict__ Bt,
                                               const float* __restrict__ bias,
                                               void* __restrict__ Dv,
                                               int N, int KB) {
    extern __shared__ uint32_t dsm[];
    const int tid = threadIdx.x, lane = tid & 31, warp = tid >> 5;
    const int wm = warp >> 1, wn = warp & 1;
    const int bx = blockIdx.x, by = blockIdx.y;
    const uint32_t sb = smem_u32(dsm);

    const uint32_t* Asrc = At + (size_t)by * KB * 1024;
    const uint32_t* Bsrc = Bt + (size_t)bx * KB * 1024;
    const int KT = KB >> 1;

    auto issue = [&](int st, int kt2) {
        uint32_t d = sb + st * 16384 + tid * 16;
        const uint32_t* sa = Asrc + (size_t)kt2 * 2048 + tid * 4;
        const uint32_t* sbp = Bsrc + (size_t)kt2 * 2048 + tid * 4;
#pragma unroll
        for (int c = 0; c < 4; c++) {
            CP_ASYNC16(d + c * 2048,        sa  + c * 512);
            CP_ASYNC16(d + 8192 + c * 2048, sbp + c * 512);
        }
    };

    for (int p = 0; p < 3; p++) { if (p < KT) issue(p, p); CP_COMMIT(); }

    float acc[4][8][4];
#pragma unroll
    for (int i = 0; i < 4; i++)
#pragma unroll
        for (int j = 0; j < 8; j++)
#pragma unroll
            for (int r = 0; r < 4; r++) acc[i][j][r] = 0.f;

    for (int kt = 0; kt < KT; kt++) {
        const int st = kt & 3;
        CP_WAIT2();
        __syncthreads();
        if (kt + 3 < KT) issue((kt + 3) & 3, kt + 3);
        CP_COMMIT();
#pragma unroll
        for (int s2 = 0; s2 < 2; s2++) {
            const uint32_t* As = dsm + st * 4096 + s2 * 1024;
            const uint32_t* Bs = dsm + st * 4096 + 2048 + s2 * 1024;
            uint32_t af[4][4], bf[8][2];
#pragma unroll
            for (int mt = 0; mt < 4; mt++)
                *reinterpret_cast<uint4*>(af[mt]) =
                    *reinterpret_cast<const uint4*>(&As[(wm * 4 + mt) * 128 + lane * 4]);
#pragma unroll
            for (int nt = 0; nt < 8; nt++)
                *reinterpret_cast<uint2*>(bf[nt]) =
                    *reinterpret_cast<const uint2*>(&Bs[(wn * 8 + nt) * 64 + lane * 2]);
#pragma unroll
            for (int mt = 0; mt < 4; mt++)
#pragma unroll
                for (int nt = 0; nt < 8; nt++)
                    mma_f16(acc[mt][nt], af[mt], bf[nt]);
        }
    }

#pragma unroll
    for (int mt = 0; mt < 4; mt++) {
        const int row0 = by * 128 + wm * 64 + mt * 16 + (lane >> 2);
#pragma unroll
        for (int nt = 0; nt < 8; nt++) {
            const int col0 = bx * 128 + wn * 64 + nt * 8 + (lane & 3) * 2;
#pragma unroll
            for (int hf = 0; hf < 2; hf++) {
                const int row = row0 + hf * 8;
                float v0 = acc[mt][nt][hf * 2 + 0];
                float v1 = acc[mt][nt][hf * 2 + 1];
                if (EPI != 4) { v0 += bias[col0]; v1 += bias[col0 + 1]; }
                if (EPI == 1) {
                    float* drow = (float*)Dv + (size_t)row * N + col0;
                    drow[0] += v0; drow[1] += v1;
                } else if (EPI == 2) {
                    v0 = 0.5f * v0 * (1.f + erff(v0 * 0.70710678118654752f));
                    v1 = 0.5f * v1 * (1.f + erff(v1 * 0.70710678118654752f));
                    ((uint32_t*)Dv)[a_widx(row, col0, N >> 4)] = h2pack(v0, v1);
                } else if (EPI == 3) {
                    __half* drow = (__half*)Dv + (size_t)row * N + col0;
                    *reinterpret_cast<__half2*>(drow) = __floats2half2_rn(v0, v1);
                } else {
                    float* drow = (float*)Dv + (size_t)row * N;
                    if (col0 < N)     drow[col0]     = v0;
                    if (col0 + 1 < N) drow[col0 + 1] = v1;
                }
            }
        }
    }
}

// =============================================================================
// 64x128-tile GEMM (EPI1 residual+bias) for proj/fc2.
// 8 warps, warp tile 32x32, 12KB/stage = 48KB.
// =============================================================================
__global__ void __launch_bounds__(256) hgemm_t64(const uint32_t* __restrict__ At,
                                                 const uint32_t* __restrict__ Bt,
                                                 const float* __restrict__ bias,
                                                 float* __restrict__ D,
                                                 int N, int KB) {
    extern __shared__ uint32_t dsm[];
    const int tid = threadIdx.x, lane = tid & 31, warp = tid >> 5;
    const int wm = warp >> 2, wn = warp & 3;
    const int bx = blockIdx.x, by = blockIdx.y;
    const uint32_t sb = smem_u32(dsm);

    const uint32_t* Asrc = At + (size_t)(by >> 1) * KB * 1024 + (by & 1) * 512;
    const uint32_t* Bsrc = Bt + (size_t)bx * KB * 1024;
    const int KT = KB >> 1;

    const int aks = tid >> 7;
    const int aw  = (tid & 127) * 4;

    auto issue = [&](int st, int kt2) {
        uint32_t d = sb + st * 12288;
        const uint32_t* sa = Asrc + (size_t)(kt2 * 2 + aks) * 1024 + aw;
        CP_ASYNC16(d + tid * 16, sa);
        const uint32_t* sbp = Bsrc + (size_t)kt2 * 2048 + tid * 4;
        CP_ASYNC16(d + 4096 + tid * 16, sbp);
        CP_ASYNC16(d + 8192 + tid * 16, sbp + 1024);
    };

    for (int p = 0; p < 3; p++) { if (p < KT) issue(p, p); CP_COMMIT(); }

    float acc[2][4][4];
#pragma unroll
    for (int i = 0; i < 2; i++)
#pragma unroll
        for (int j = 0; j < 4; j++)
#pragma unroll
            for (int r = 0; r < 4; r++) acc[i][j][r] = 0.f;

    for (int kt = 0; kt < KT; kt++) {
        const int st = kt & 3;
        CP_WAIT2();
        __syncthreads();
        if (kt + 3 < KT) issue((kt + 3) & 3, kt + 3);
        CP_COMMIT();
#pragma unroll
        for (int s2 = 0; s2 < 2; s2++) {
            const uint32_t* As = dsm + st * 3072 + s2 * 512;
            const uint32_t* Bs = dsm + st * 3072 + 1024 + s2 * 1024;
            uint32_t af[2][4], bf[4][2];
#pragma unroll
            for (int mt = 0; mt < 2; mt++)
                *reinterpret_cast<uint4*>(af[mt]) =
                    *reinterpret_cast<const uint4*>(&As[(wm * 2 + mt) * 128 + lane * 4]);
#pragma unroll
            for (int nt = 0; nt < 4; nt++)
                *reinterpret_cast<uint2*>(bf[nt]) =
                    *reinterpret_cast<const uint2*>(&Bs[(wn * 4 + nt) * 64 + lane * 2]);
#pragma unroll
            for (int mt = 0; mt < 2; mt++)
#pragma unroll
                for (int nt = 0; nt < 4; nt++)
                    mma_f16(acc[mt][nt], af[mt], bf[nt]);
        }
    }

#pragma unroll
    for (int mt = 0; mt < 2; mt++) {
        const int row0 = by * 64 + wm * 32 + mt * 16 + (lane >> 2);
#pragma unroll
        for (int nt = 0; nt < 4; nt++) {
            const int col0 = bx * 128 + wn * 32 + nt * 8 + (lane & 3) * 2;
#pragma unroll
            for (int hf = 0; hf < 2; hf++) {
                const int row = row0 + hf * 8;
                float* drow = D + (size_t)row * N + col0;
                drow[0] += acc[mt][nt][hf * 2 + 0] + bias[col0];
                drow[1] += acc[mt][nt][hf * 2 + 1] + bias[col0 + 1];
            }
        }
    }
}

// =============================================================================
// Flash attention (fp16 MMA, fp32 softmax/accum) — unchanged.
// =============================================================================
__global__ void __launch_bounds__(256) flash_attn(const __half* __restrict__ qkv,
                                                  uint32_t* __restrict__ yt) {
    __shared__ uint32_t sK[2][2048];
    __shared__ uint32_t sV[2][2048];
    uint32_t* sq = &sK[0][0];

    const int tid = threadIdx.x, lane = tid & 31, warp = tid >> 5;
    const int qt = blockIdx.x;
    const int bh = blockIdx.y, b = bh >> 4, h = bh & 15;

    const __half* qbase = qkv + (size_t)(b * NT + qt * 128) * C3 + h * NHD;
    const __half* kbase = qkv + (size_t)(b * NT) * C3 + NC + h * NHD;
    const __half* vbase = qkv + (size_t)(b * NT) * C3 + 2 * NC + h * NHD;

    uint32_t af[4][4];
    {
        const int r = tid >> 1, hfq = tid & 1;
        const __half* qp = qbase + (size_t)r * C3 + hfq * 32;
        uint4 v0 = *reinterpret_cast<const uint4*>(qp);
        uint4 v1 = *reinterpret_cast<const uint4*>(qp + 8);
        uint4 v2 = *reinterpret_cast<const uint4*>(qp + 16);
        uint4 v3 = *reinterpret_cast<const uint4*>(qp + 24);
        const int ab0 = (2 * hfq) * 1024 + (r >> 4) * 128 + (r & 7) * 16 + ((r >> 3) & 1);
        const int ab1 = ab0 + 1024;
        const uint32_t* w0 = reinterpret_cast<const uint32_t*>(&v0);
        const uint32_t* w1 = reinterpret_cast<const uint32_t*>(&v1);
        const uint32_t* w2 = reinterpret_cast<const uint32_t*>(&v2);
        const uint32_t* w3 = reinterpret_cast<const uint32_t*>(&v3);
#pragma unroll
        for (int i = 0; i < 4; i++) {
            sq[ab0 + i * 4]     = w0[i];
            sq[ab0 + i * 4 + 2] = w1[i];
            sq[ab1 + i * 4]     = w2[i];
            sq[ab1 + i * 4 + 2] = w3[i];
        }
        __syncthreads();
#pragma unroll
        for (int ks = 0; ks < 4; ks++)
            *reinterpret_cast<uint4*>(af[ks]) =
                *reinterpret_cast<const uint4*>(&sq[ks * 1024 + warp * 128 + lane * 4]);
        __syncthreads();
    }

    const int knr = tid >> 2, kq = tid & 3;
    const int kb  = kq * 512 + (knr >> 3) * 64 + (knr & 7) * 8;
    const int vpp = tid >> 3, vn0 = (tid & 7) * 8;
    const int vks = vpp >> 3, vjj = vpp & 7;
    int vst[4];
#pragma unroll
    for (int i = 0; i < 4; i++) {
        int n = vn0 + 2 * i;
        vst[i] = vks * 512 + (n >> 3) * 64 + ((n & 7) * 4 + (vjj & 3)) * 2 + (vjj >> 2);
    }

    float oacc[8][4];
#pragma unroll
    for (int nt = 0; nt < 8; nt++)
#pragma unroll
        for (int i = 0; i < 4; i++) oacc[nt][i] = 0.f;
    float mrun0 = -1e30f, mrun1 = -1e30f, lrun0 = 0.f, lrun1 = 0.f;

    uint4 ku0, ku1, va, vb;
    {
        const __half* kp = kbase + (size_t)knr * C3 + kq * 16;
        ku0 = *reinterpret_cast<const uint4*>(kp);
        ku1 = *reinterpret_cast<const uint4*>(kp + 8);
        const __half* vp = vbase + (size_t)(2 * vpp) * C3 + vn0;
        va = *reinterpret_cast<const uint4*>(vp);
        vb = *reinterpret_cast<const uint4*>(vp + C3);
        const uint32_t* kw0 = reinterpret_cast<const uint32_t*>(&ku0);
        const uint32_t* kw1 = reinterpret_cast<const uint32_t*>(&ku1);
        const uint32_t* vwa = reinterpret_cast<const uint32_t*>(&va);
        const uint32_t* vwb = reinterpret_cast<const uint32_t*>(&vb);
#pragma unroll
        for (int i = 0; i < 4; i++) {
            sK[0][kb + i * 2]     = kw0[i];
            sK[0][kb + i * 2 + 1] = kw1[i];
            sV[0][vst[i]]     = __byte_perm(vwa[i], vwb[i], 0x5410);
            sV[0][vst[i] + 8] = __byte_perm(vwa[i], vwb[i], 0x7632);
        }
    }
    __syncthreads();

    for (int kt = 0; kt < 16; kt++) {
        const int s = kt & 1;
        if (kt + 1 < 16) {
            const __half* kp = kbase + (size_t)((kt + 1) * 64 + knr) * C3 + kq * 16;
            ku0 = *reinterpret_cast<const uint4*>(kp);
            ku1 = *reinterpret_cast<const uint4*>(kp + 8);
            const __half* vp = vbase + (size_t)((kt + 1) * 64 + 2 * vpp) * C3 + vn0;
            va = *reinterpret_cast<const uint4*>(vp);
            vb = *reinterpret_cast<const uint4*>(vp + C3);
        }

        float sacc[8][4];
#pragma unroll
        for (int nt = 0; nt < 8; nt++) {
#pragma unroll
            for (int i = 0; i < 4; i++) sacc[nt][i] = 0.f;
#pragma unroll
            for (int ks = 0; ks < 4; ks++) {
                uint32_t bfr[2];
                *reinterpret_cast<uint2*>(bfr) =
                    *reinterpret_cast<const uint2*>(&sK[s][ks * 512 + nt * 64 + lane * 2]);
                mma_f16(sacc[nt], af[ks], bfr);
            }
        }

        float m0 = -1e30f, m1 = -1e30f;
#pragma unroll
        for (int nt = 0; nt < 8; nt++) {
#pragma unroll
            for (int i = 0; i < 4; i++) sacc[nt][i] *= 0.125f;
            m0 = fmaxf(m0, fmaxf(sacc[nt][0], sacc[nt][1]));
            m1 = fmaxf(m1, fmaxf(sacc[nt][2], sacc[nt][3]));
        }
        m0 = fmaxf(m0, __shfl_xor_sync(0xffffffffu, m0, 1));
        m0 = fmaxf(m0, __shfl_xor_sync(0xffffffffu, m0, 2));
        m1 = fmaxf(m1, __shfl_xor_sync(0xffffffffu, m1, 1));
        m1 = fmaxf(m1, __shfl_xor_sync(0xffffffffu, m1, 2));
        const float mn0 = fmaxf(mrun0, m0), mn1 = fmaxf(mrun1, m1);
        const float al0 = __expf(mrun0 - mn0), al1 = __expf(mrun1 - mn1);
        mrun0 = mn0; mrun1 = mn1;

        float r0 = 0.f, r1 = 0.f;
#pragma unroll
        for (int nt = 0; nt < 8; nt++) {
            sacc[nt][0] = __expf(sacc[nt][0] - mn0);
            sacc[nt][1] = __expf(sacc[nt][1] - mn0);
            sacc[nt][2] = __expf(sacc[nt][2] - mn1);
            sacc[nt][3] = __expf(sacc[nt][3] - mn1);
            r0 += sacc[nt][0] + sacc[nt][1];
            r1 += sacc[nt][2] + sacc[nt][3];
        }
        r0 += __shfl_xor_sync(0xffffffffu, r0, 1);
        r0 += __shfl_xor_sync(0xffffffffu, r0, 2);
        r1 += __shfl_xor_sync(0xffffffffu, r1, 1);
        r1 += __shfl_xor_sync(0xffffffffu, r1, 2);
        lrun0 = lrun0 * al0 + r0;
        lrun1 = lrun1 * al1 + r1;

#pragma unroll
        for (int nt = 0; nt < 8; nt++) {
            oacc[nt][0] *= al0; oacc[nt][1] *= al0;
            oacc[nt][2] *= al1; oacc[nt][3] *= al1;
        }

        uint32_t pf[4][4];
#pragma unroll
        for (int ks = 0; ks < 4; ks++) {
            pf[ks][0] = h2pack(sacc[2 * ks][0],     sacc[2 * ks][1]);
            pf[ks][1] = h2pack(sacc[2 * ks][2],     sacc[2 * ks][3]);
            pf[ks][2] = h2pack(sacc[2 * ks + 1][0], sacc[2 * ks + 1][1]);
            pf[ks][3] = h2pack(sacc[2 * ks + 1][2], sacc[2 * ks + 1][3]);
        }
#pragma unroll
        for (int nt = 0; nt < 8; nt++) {
#pragma unroll
            for (int ks = 0; ks < 4; ks++) {
                uint32_t bfr[2];
                *reinterpret_cast<uint2*>(bfr) =
                    *reinterpret_cast<const uint2*>(&sV[s][ks * 512 + nt * 64 + lane * 2]);
                mma_f16(oacc[nt], pf[ks], bfr);
            }
        }

        if (kt + 1 < 16) {
            const int ns = s ^ 1;
            const uint32_t* kw0 = reinterpret_cast<const uint32_t*>(&ku0);
            const uint32_t* kw1 = reinterpret_cast<const uint32_t*>(&ku1);
            const uint32_t* vwa = reinterpret_cast<const uint32_t*>(&va);
            const uint32_t* vwb = reinterpret_cast<const uint32_t*>(&vb);
#pragma unroll
            for (int i = 0; i < 4; i++) {
                sK[ns][kb + i * 2]     = kw0[i];
                sK[ns][kb + i * 2 + 1] = kw1[i];
                sV[ns][vst[i]]     = __byte_perm(vwa[i], vwb[i], 0x5410);
                sV[ns][vst[i] + 8] = __byte_perm(vwa[i], vwb[i], 0x7632);
            }
        }
        __syncthreads();
    }

    const float inv0 = 1.f / lrun0, inv1 = 1.f / lrun1;
    const int rowA = b * NT + qt * 128 + warp * 16 + (lane >> 2);
    const int colb = h * NHD + (lane & 3) * 2;
#pragma unroll
    for (int nt = 0; nt < 8; nt++) {
        yt[a_widx(rowA,     colb + nt * 8, 64)] =
            h2pack(oacc[nt][0] * inv0, oacc[nt][1] * inv0);
        yt[a_widx(rowA + 8, colb + nt * 8, 64)] =
            h2pack(oacc[nt][2] * inv1, oacc[nt][3] * inv1);
    }
}

// ---------------- host orchestration -----------------------------------------
#define SMEM_W   65536
#define SMEM_T64 49152

extern "C" void kernel_launch(void* const* d_in, const int* in_sizes, int n_in,
                              void* d_out, int out_size) {
    const int*   ids    = (const int*)  d_in[0];
    const float* wte    = (const float*)d_in[1];
    const float* wpe    = (const float*)d_in[2];
    const float* ln1_w  = (const float*)d_in[3];
    const float* ln1_b  = (const float*)d_in[4];
    const float* attn_w = (const float*)d_in[5];
    const float* attn_b = (const float*)d_in[6];
    const float* proj_w = (const float*)d_in[7];
    const float* proj_b = (const float*)d_in[8];
    const float* ln2_w  = (const float*)d_in[9];
    const float* ln2_b  = (const float*)d_in[10];
    const float* fc_w   = (const float*)d_in[11];
    const float* fc_b   = (const float*)d_in[12];
    const float* fc2_w  = (const float*)d_in[13];
    const float* fc2_b  = (const float*)d_in[14];
    const float* lnf_w  = (const float*)d_in[15];
    const float* lnf_b  = (const float*)d_in[16];
    float* out = (float*)d_out;

    float* x;
    __half* qkv16;
    uint32_t *h16t, *y16t, *mlp16t, *wa, *wp, *wf, *wf2, *wv;
    cudaGetSymbolAddress((void**)&x,      g_x);
    cudaGetSymbolAddress((void**)&qkv16,  g_qkv16);
    cudaGetSymbolAddress((void**)&h16t,   g_h16t);
    cudaGetSymbolAddress((void**)&y16t,   g_y16t);
    cudaGetSymbolAddress((void**)&mlp16t, g_mlp16t);
    cudaGetSymbolAddress((void**)&wa,     w_attn_t);
    cudaGetSymbolAddress((void**)&wp,     w_proj_t);
    cudaGetSymbolAddress((void**)&wf,     w_fc_t);
    cudaGetSymbolAddress((void**)&wf2,    w_fc2_t);
    cudaGetSymbolAddress((void**)&wv,     w_wte_t);

    cudaFuncSetAttribute(hgemm_w<1>, cudaFuncAttributeMaxDynamicSharedMemorySize, SMEM_W);
    cudaFuncSetAttribute(hgemm_w<2>, cudaFuncAttributeMaxDynamicSharedMemorySize, SMEM_W);
    cudaFuncSetAttribute(hgemm_w<3>, cudaFuncAttributeMaxDynamicSharedMemorySize, SMEM_W);
    cudaFuncSetAttribute(hgemm_w<4>, cudaFuncAttributeMaxDynamicSharedMemorySize, SMEM_W);
    cudaFuncSetAttribute(hgemm_t64,  cudaFuncAttributeMaxDynamicSharedMemorySize, SMEM_T64);

    embed_kernel<<<NTOK, 256>>>(ids, wte, wpe, x);
    cvt_all<<<74304, 256>>>(attn_w, proj_w, fc_w, fc2_w, wte, wa, wp, wf, wf2, wv);

    const size_t wa_s = (size_t)NC * C3 / 2, wp_s = (size_t)NC * NC / 2;
    const size_t wf_s = (size_t)NC * C4 / 2, wf2_s = (size_t)C4 * NC / 2;

    for (int l = 0; l < NL; l++) {
        ln_kernel<<<NTOK, 256>>>(x, ln1_w + (size_t)l * NC, ln1_b + (size_t)l * NC, h16t);
        hgemm_w<3><<<dim3(C3 / 128, NTOK / 128), 128, SMEM_W>>>(
            h16t, wa + l * wa_s, attn_b + (size_t)l * C3, qkv16, C3, 64);
        flash_attn<<<dim3(NT / 128, NB * NH), 256>>>(qkv16, y16t);
        hgemm_t64<<<dim3(NC / 128, NTOK / 64), 256, SMEM_T64>>>(
            y16t, wp + l * wp_s, proj_b + (size_t)l * NC, x, NC, 64);
        ln_kernel<<<NTOK, 256>>>(x, ln2_w + (size_t)l * NC, ln2_b + (size_t)l * NC, h16t);
        hgemm_w<2><<<dim3(C4 / 128, NTOK / 128), 128, SMEM_W>>>(
            h16t, wf + l * wf_s, fc_b + (size_t)l * C4, mlp16t, C4, 64);
        hgemm_t64<<<dim3(NC / 128, NTOK / 64), 256, SMEM_T64>>>(
            mlp16t, wf2 + l * wf2_s, fc2_b + (size_t)l * NC, x, NC, 256);
    }

    ln_kernel<<<NTOK, 256>>>(x, lnf_w, lnf_b, h16t);
    hgemm_w<4><<<dim3(NVP / 128, NTOK / 128), 128, SMEM_W>>>(
        h16t, wv, nullptr, out, NV, 64);
}

// round 14
// speedup vs baseline: 1.1172x; 1.0555x over previous
#include <cuda_runtime.h>
#include <cuda_fp16.h>
#include <math.h>
#include <stdint.h>

// Problem dims
#define NL   8
#define NB   2
#define NT   1024
#define NC   1024
#define NH   16
#define NHD  64
#define NV   50257
#define NVP  50304
#define NTOK 2048
#define C3   3072
#define C4   4096

// ---------------- scratch ----------------------------------------------------
__device__ float    g_x    [NTOK * NC];
__device__ __half   g_qkv16[NTOK * C3];
__device__ uint32_t g_h16t [NTOK * NC / 2];
__device__ uint32_t g_y16t [NTOK * NC / 2];
__device__ uint32_t g_mlp16t[NTOK * C4 / 2];
__device__ uint32_t w_attn_t[(size_t)NL * NC * C3 / 2];
__device__ uint32_t w_proj_t[(size_t)NL * NC * NC / 2];
__device__ uint32_t w_fc_t  [(size_t)NL * NC * C4 / 2];
__device__ uint32_t w_fc2_t [(size_t)NL * C4 * NC / 2];
__device__ uint32_t w_wte_t [(size_t)NVP * NC / 2];

// ---------------- helpers ----------------------------------------------------
__device__ __forceinline__ void mma_f16(float* d, const uint32_t* a, const uint32_t* b) {
    asm volatile(
        "mma.sync.aligned.m16n8k16.row.col.f32.f16.f16.f32 "
        "{%0,%1,%2,%3}, {%4,%5,%6,%7}, {%8,%9}, {%0,%1,%2,%3};"
        : "+f"(d[0]), "+f"(d[1]), "+f"(d[2]), "+f"(d[3])
        : "r"(a[0]), "r"(a[1]), "r"(a[2]), "r"(a[3]), "r"(b[0]), "r"(b[1]));
}
__device__ __forceinline__ uint32_t h2pack(float lo, float hi) {
    __half2 h = __floats2half2_rn(lo, hi);
    return *reinterpret_cast<uint32_t*>(&h);
}
__device__ __forceinline__ uint32_t smem_u32(const void* p) {
    uint32_t a;
    asm("{ .reg .u64 t; cvta.to.shared.u64 t, %1; cvt.u32.u64 %0, t; }" : "=r"(a) : "l"(p));
    return a;
}
#define CP_ASYNC16(dst, src) \
    asm volatile("cp.async.cg.shared.global [%0], [%1], 16;" :: "r"(dst), "l"(src))
#define CP_COMMIT() asm volatile("cp.async.commit_group;" ::: "memory")
#define CP_WAIT2()  asm volatile("cp.async.wait_group 2;" ::: "memory")

__device__ __forceinline__ size_t a_widx(int row, int col, int KB) {
    return ((size_t)(row >> 7) * KB + (col >> 4)) * 1024
         + ((row >> 4) & 7) * 128 + (row & 7) * 16 + ((row >> 3) & 1)
         + ((col >> 1) & 3) * 4 + ((col >> 3) & 1) * 2;
}

__device__ __forceinline__ float block_sum(float v) {
    __shared__ float sh[8];
    int lane = threadIdx.x & 31, w = threadIdx.x >> 5;
#pragma unroll
    for (int o = 16; o; o >>= 1) v += __shfl_xor_sync(0xffffffffu, v, o);
    if (lane == 0) sh[w] = v;
    __syncthreads();
    v = sh[0] + sh[1] + sh[2] + sh[3] + sh[4] + sh[5] + sh[6] + sh[7];
    __syncthreads();
    return v;
}

// ---------------- unified weight conversion (ONE launch, smem-staged) ---------
__global__ void __launch_bounds__(256) cvt_all(
    const float* __restrict__ attn_w, const float* __restrict__ proj_w,
    const float* __restrict__ fc_w,   const float* __restrict__ fc2_w,
    const float* __restrict__ wte,
    uint32_t* __restrict__ wa, uint32_t* __restrict__ wp,
    uint32_t* __restrict__ wf, uint32_t* __restrict__ wf2,
    uint32_t* __restrict__ wv)
{
    __shared__ float    sf[2048];
    __shared__ uint32_t so[1024];
    const int bid = blockIdx.x;
    const int t = threadIdx.x;

    uint32_t* dout;
    if (bid < 49152) {
        const float* src; uint32_t* dst; int K, N, l, nt, kb;
        if (bid < 12288) {
            K = NC; N = C3; int id = bid;
            kb = id & 63; nt = (id >> 6) % 24; l = (id >> 6) / 24;
            src = attn_w; dst = wa;
        } else if (bid < 16384) {
            K = NC; N = NC; int id = bid - 12288;
            kb = id & 63; nt = (id >> 6) & 7; l = id >> 9;
            src = proj_w; dst = wp;
        } else if (bid < 32768) {
            K = NC; N = C4; int id = bid - 16384;
            kb = id & 63; nt = (id >> 6) & 31; l = id >> 11;
            src = fc_w; dst = wf;
        } else {
            K = C4; N = NC; int id = bid - 32768;
            kb = id & 255; nt = (id >> 8) & 7; l = id >> 11;
            src = fc2_w; dst = wf2;
        }
        const float* s = src + (size_t)l * K * N;
        dout = dst + (((size_t)l * (N >> 7) + nt) * (K >> 4) + kb) * 1024;

        float4* sf4 = reinterpret_cast<float4*>(sf);
#pragma unroll
        for (int i = 0; i < 2; i++) {
            int idx = t + 256 * i;
            int row = idx >> 5, c4 = idx & 31;
            sf4[row * 32 + c4] = *reinterpret_cast<const float4*>(
                s + (size_t)(kb * 16 + row) * N + nt * 128 + c4 * 4);
        }
        __syncthreads();
#pragma unroll
        for (int w = 0; w < 4; w++) {
            int wid = t + 256 * w;
            int jj = wid >> 7, n = wid & 127;
            so[(n >> 3) * 64 + (n & 7) * 8 + (jj & 3) * 2 + (jj >> 2)] =
                h2pack(sf[2 * jj * 128 + n], sf[(2 * jj + 1) * 128 + n]);
        }
    } else {
        int id = bid - 49152;
        int kb = id & 63, nt = id >> 6;
        dout = wv + ((size_t)nt * 64 + kb) * 1024;

        float4* sf4 = reinterpret_cast<float4*>(sf);
#pragma unroll
        for (int i = 0; i < 2; i++) {
            int idx = t + 256 * i;
            int nr = idx >> 2, k4 = idx & 3;
            int gn = nt * 128 + nr;
            float4 v = make_float4(0.f, 0.f, 0.f, 0.f);
            if (gn < NV)
                v = *reinterpret_cast<const float4*>(
                    wte + (size_t)gn * NC + kb * 16 + k4 * 4);
            sf4[nr * 4 + k4] = v;
        }
        __syncthreads();
#pragma unroll
        for (int w = 0; w < 4; w++) {
            int wid = t + 256 * w;
            int nr = wid >> 3, jj = wid & 7;
            so[(nr >> 3) * 64 + (nr & 7) * 8 + (jj & 3) * 2 + (jj >> 2)] =
                h2pack(sf[nr * 16 + 2 * jj], sf[nr * 16 + 2 * jj + 1]);
        }
    }
    __syncthreads();
    reinterpret_cast<uint4*>(dout)[t] = reinterpret_cast<const uint4*>(so)[t];
}

// ---------------- embedding / layernorm --------------------------------------
__global__ void embed_kernel(const int* __restrict__ ids,
                             const float* __restrict__ wte,
                             const float* __restrict__ wpe,
                             float* __restrict__ x) {
    int tok = blockIdx.x, t = tok & (NT - 1), id = ids[tok];
    const float* src = wte + (size_t)id * NC;
    const float* pp  = wpe + (size_t)t * NC;
    float* dst = x + (size_t)tok * NC;
    for (int c = threadIdx.x; c < NC; c += blockDim.x) dst[c] = src[c] + pp[c];
}

__global__ void __launch_bounds__(256) ln_kernel(const float* __restrict__ x,
                                                 const float* __restrict__ w,
                                                 const float* __restrict__ b,
                                                 uint32_t* __restrict__ o) {
    int row = blockIdx.x, tid = threadIdx.x;
    const float2* xr = reinterpret_cast<const float2*>(x + (size_t)row * NC);
    float2 v[2]; float s = 0.f;
#pragma unroll
    for (int i = 0; i < 2; i++) { v[i] = xr[tid + 256 * i]; s += v[i].x + v[i].y; }
    s = block_sum(s);
    float mean = s * (1.f / NC), s2 = 0.f;
#pragma unroll
    for (int i = 0; i < 2; i++) {
        float dx = v[i].x - mean, dy = v[i].y - mean;
        s2 += dx * dx + dy * dy;
    }
    s2 = block_sum(s2);
    float rstd = rsqrtf(s2 * (1.f / NC) + 1e-5f);
#pragma unroll
    for (int i = 0; i < 2; i++) {
        int col = 2 * (tid + 256 * i);
        float a0 = (v[i].x - mean) * rstd * w[col] + b[col];
        float a1 = (v[i].y - mean) * rstd * w[col + 1] + b[col + 1];
        o[a_widx(row, col, 64)] = h2pack(a0, a1);
    }
}

// =============================================================================
// 128x128-tile GEMM, 128 threads (4 warps, 2x2), warp tile 64x64.
// cp.async 4-stage (16KB/stage = 64KB).
// MB = min blocks/SM (3 forces regs<=170 -> single wave for grid<=444).
// EPI: 1 fp32 residual add (+bias)   2 GELU -> tiled fp16 (+bias)
//      3 fp16 row-major (+bias)      4 fp32 store, no bias, col<N guard
// =============================================================================
template <int EPI, int MB>
__global__ void __launch_bounds__(128, MB) hgemm_w(const uint32_t* __restrict__ At,
                                                   const uint32_t* __restrict__ Bt,
                                                   const float* __restrict__ bias,
                                                   void* __restrict__ Dv,
                                                   int N, int KB) {
    extern __shared__ uint32_t dsm[];
    const int tid = threadIdx.x, lane = tid & 31, warp = tid >> 5;
    const int wm = warp >> 1, wn = warp & 1;
    const int bx = blockIdx.x, by = blockIdx.y;
    const uint32_t sb = smem_u32(dsm);

    const uint32_t* Asrc = At + (size_t)by * KB * 1024;
    const uint32_t* Bsrc = Bt + (size_t)bx * KB * 1024;
    const int KT = KB >> 1;

    auto issue = [&](int st, int kt2) {
        uint32_t d = sb + st * 16384 + tid * 16;
        const uint32_t* sa = Asrc + (size_t)kt2 * 2048 + tid * 4;
        const uint32_t* sbp = Bsrc + (size_t)kt2 * 2048 + tid * 4;
#pragma unroll
        for (int c = 0; c < 4; c++) {
            CP_ASYNC16(d + c * 2048,        sa  + c * 512);
            CP_ASYNC16(d + 8192 + c * 2048, sbp + c * 512);
        }
    };

    for (int p = 0; p < 3; p++) { if (p < KT) issue(p, p); CP_COMMIT(); }

    float acc[4][8][4];
#pragma unroll
    for (int i = 0; i < 4; i++)
#pragma unroll
        for (int j = 0; j < 8; j++)
#pragma unroll
            for (int r = 0; r < 4; r++) acc[i][j][r] = 0.f;

    for (int kt = 0; kt < KT; kt++) {
        const int st = kt & 3;
        CP_WAIT2();
        __syncthreads();
        if (kt + 3 < KT) issue((kt + 3) & 3, kt + 3);
        CP_COMMIT();
#pragma unroll
        for (int s2 = 0; s2 < 2; s2++) {
            const uint32_t* As = dsm + st * 4096 + s2 * 1024;
            const uint32_t* Bs = dsm + st * 4096 + 2048 + s2 * 1024;
            uint32_t af[4][4], bf[8][2];
#pragma unroll
            for (int mt = 0; mt < 4; mt++)
                *reinterpret_cast<uint4*>(af[mt]) =
                    *reinterpret_cast<const uint4*>(&As[(wm * 4 + mt) * 128 + lane * 4]);
#pragma unroll
            for (int nt = 0; nt < 8; nt++)
                *reinterpret_cast<uint2*>(bf[nt]) =
                    *reinterpret_cast<const uint2*>(&Bs[(wn * 8 + nt) * 64 + lane * 2]);
#pragma unroll
            for (int mt = 0; mt < 4; mt++)
#pragma unroll
                for (int nt = 0; nt < 8; nt++)
                    mma_f16(acc[mt][nt], af[mt], bf[nt]);
        }
    }

#pragma unroll
    for (int mt = 0; mt < 4; mt++) {
        const int row0 = by * 128 + wm * 64 + mt * 16 + (lane >> 2);
#pragma unroll
        for (int nt = 0; nt < 8; nt++) {
            const int col0 = bx * 128 + wn * 64 + nt * 8 + (lane & 3) * 2;
#pragma unroll
            for (int hf = 0; hf < 2; hf++) {
                const int row = row0 + hf * 8;
                float v0 = acc[mt][nt][hf * 2 + 0];
                float v1 = acc[mt][nt][hf * 2 + 1];
                if (EPI != 4) { v0 += bias[col0]; v1 += bias[col0 + 1]; }
                if (EPI == 1) {
                    float* drow = (float*)Dv + (size_t)row * N + col0;
                    drow[0] += v0; drow[1] += v1;
                } else if (EPI == 2) {
                    v0 = 0.5f * v0 * (1.f + erff(v0 * 0.70710678118654752f));
                    v1 = 0.5f * v1 * (1.f + erff(v1 * 0.70710678118654752f));
                    ((uint32_t*)Dv)[a_widx(row, col0, N >> 4)] = h2pack(v0, v1);
                } else if (EPI == 3) {
                    __half* drow = (__half*)Dv + (size_t)row * N + col0;
                    *reinterpret_cast<__half2*>(drow) = __floats2half2_rn(v0, v1);
                } else {
                    float* drow = (float*)Dv + (size_t)row * N;
                    if (col0 < N)     drow[col0]     = v0;
                    if (col0 + 1 < N) drow[col0 + 1] = v1;
                }
            }
        }
    }
}

// =============================================================================
// 64x128-tile GEMM (EPI1 residual+bias) for proj/fc2.
// 8 warps, warp tile 32x32, 12KB/stage = 48KB.
// =============================================================================
__global__ void __launch_bounds__(256) hgemm_t64(const uint32_t* __restrict__ At,
                                                 const uint32_t* __restrict__ Bt,
                                                 const float* __restrict__ bias,
                                                 float* __restrict__ D,
                                                 int N, int KB) {
    extern __shared__ uint32_t dsm[];
    const int tid = threadIdx.x, lane = tid & 31, warp = tid >> 5;
    const int wm = warp >> 2, wn = warp & 3;
    const int bx = blockIdx.x, by = blockIdx.y;
    const uint32_t sb = smem_u32(dsm);

    const uint32_t* Asrc = At + (size_t)(by >> 1) * KB * 1024 + (by & 1) * 512;
    const uint32_t* Bsrc = Bt + (size_t)bx * KB * 1024;
    const int KT = KB >> 1;

    const int aks = tid >> 7;
    const int aw  = (tid & 127) * 4;

    auto issue = [&](int st, int kt2) {
        uint32_t d = sb + st * 12288;
        const uint32_t* sa = Asrc + (size_t)(kt2 * 2 + aks) * 1024 + aw;
        CP_ASYNC16(d + tid * 16, sa);
        const uint32_t* sbp = Bsrc + (size_t)kt2 * 2048 + tid * 4;
        CP_ASYNC16(d + 4096 + tid * 16, sbp);
        CP_ASYNC16(d + 8192 + tid * 16, sbp + 1024);
    };

    for (int p = 0; p < 3; p++) { if (p < KT) issue(p, p); CP_COMMIT(); }

    float acc[2][4][4];
#pragma unroll
    for (int i = 0; i < 2; i++)
#pragma unroll
        for (int j = 0; j < 4; j++)
#pragma unroll
            for (int r = 0; r < 4; r++) acc[i][j][r] = 0.f;

    for (int kt = 0; kt < KT; kt++) {
        const int st = kt & 3;
        CP_WAIT2();
        __syncthreads();
        if (kt + 3 < KT) issue((kt + 3) & 3, kt + 3);
        CP_COMMIT();
#pragma unroll
        for (int s2 = 0; s2 < 2; s2++) {
            const uint32_t* As = dsm + st * 3072 + s2 * 512;
            const uint32_t* Bs = dsm + st * 3072 + 1024 + s2 * 1024;
            uint32_t af[2][4], bf[4][2];
#pragma unroll
            for (int mt = 0; mt < 2; mt++)
                *reinterpret_cast<uint4*>(af[mt]) =
                    *reinterpret_cast<const uint4*>(&As[(wm * 2 + mt) * 128 + lane * 4]);
#pragma unroll
            for (int nt = 0; nt < 4; nt++)
                *reinterpret_cast<uint2*>(bf[nt]) =
                    *reinterpret_cast<const uint2*>(&Bs[(wn * 4 + nt) * 64 + lane * 2]);
#pragma unroll
            for (int mt = 0; mt < 2; mt++)
#pragma unroll
                for (int nt = 0; nt < 4; nt++)
                    mma_f16(acc[mt][nt], af[mt], bf[nt]);
        }
    }

#pragma unroll
    for (int mt = 0; mt < 2; mt++) {
        const int row0 = by * 64 + wm * 32 + mt * 16 + (lane >> 2);
#pragma unroll
        for (int nt = 0; nt < 4; nt++) {
            const int col0 = bx * 128 + wn * 32 + nt * 8 + (lane & 3) * 2;
#pragma unroll
            for (int hf = 0; hf < 2; hf++) {
                const int row = row0 + hf * 8;
                float* drow = D + (size_t)row * N + col0;
                drow[0] += acc[mt][nt][hf * 2 + 0] + bias[col0];
                drow[1] += acc[mt][nt][hf * 2 + 1] + bias[col0 + 1];
            }
        }
    }
}

// =============================================================================
// Flash attention (fp16 MMA, fp32 softmax/accum) — unchanged.
// =============================================================================
__global__ void __launch_bounds__(256) flash_attn(const __half* __restrict__ qkv,
                                                  uint32_t* __restrict__ yt) {
    __shared__ uint32_t sK[2][2048];
    __shared__ uint32_t sV[2][2048];
    uint32_t* sq = &sK[0][0];

    const int tid = threadIdx.x, lane = tid & 31, warp = tid >> 5;
    const int qt = blockIdx.x;
    const int bh = blockIdx.y, b = bh >> 4, h = bh & 15;

    const __half* qbase = qkv + (size_t)(b * NT + qt * 128) * C3 + h * NHD;
    const __half* kbase = qkv + (size_t)(b * NT) * C3 + NC + h * NHD;
    const __half* vbase = qkv + (size_t)(b * NT) * C3 + 2 * NC + h * NHD;

    uint32_t af[4][4];
    {
        const int r = tid >> 1, hfq = tid & 1;
        const __half* qp = qbase + (size_t)r * C3 + hfq * 32;
        uint4 v0 = *reinterpret_cast<const uint4*>(qp);
        uint4 v1 = *reinterpret_cast<const uint4*>(qp + 8);
        uint4 v2 = *reinterpret_cast<const uint4*>(qp + 16);
        uint4 v3 = *reinterpret_cast<const uint4*>(qp + 24);
        const int ab0 = (2 * hfq) * 1024 + (r >> 4) * 128 + (r & 7) * 16 + ((r >> 3) & 1);
        const int ab1 = ab0 + 1024;
        const uint32_t* w0 = reinterpret_cast<const uint32_t*>(&v0);
        const uint32_t* w1 = reinterpret_cast<const uint32_t*>(&v1);
        const uint32_t* w2 = reinterpret_cast<const uint32_t*>(&v2);
        const uint32_t* w3 = reinterpret_cast<const uint32_t*>(&v3);
#pragma unroll
        for (int i = 0; i < 4; i++) {
            sq[ab0 + i * 4]     = w0[i];
            sq[ab0 + i * 4 + 2] = w1[i];
            sq[ab1 + i * 4]     = w2[i];
            sq[ab1 + i * 4 + 2] = w3[i];
        }
        __syncthreads();
#pragma unroll
        for (int ks = 0; ks < 4; ks++)
            *reinterpret_cast<uint4*>(af[ks]) =
                *reinterpret_cast<const uint4*>(&sq[ks * 1024 + warp * 128 + lane * 4]);
        __syncthreads();
    }

    const int knr = tid >> 2, kq = tid & 3;
    const int kb  = kq * 512 + (knr >> 3) * 64 + (knr & 7) * 8;
    const int vpp = tid >> 3, vn0 = (tid & 7) * 8;
    const int vks = vpp >> 3, vjj = vpp & 7;
    int vst[4];
#pragma unroll
    for (int i = 0; i < 4; i++) {
        int n = vn0 + 2 * i;
        vst[i] = vks * 512 + (n >> 3) * 64 + ((n & 7) * 4 + (vjj & 3)) * 2 + (vjj >> 2);
    }

    float oacc[8][4];
#pragma unroll
    for (int nt = 0; nt < 8; nt++)
#pragma unroll
        for (int i = 0; i < 4; i++) oacc[nt][i] = 0.f;
    float mrun0 = -1e30f, mrun1 = -1e30f, lrun0 = 0.f, lrun1 = 0.f;

    uint4 ku0, ku1, va, vb;
    {
        const __half* kp = kbase + (size_t)knr * C3 + kq * 16;
        ku0 = *reinterpret_cast<const uint4*>(kp);
        ku1 = *reinterpret_cast<const uint4*>(kp + 8);
        const __half* vp = vbase + (size_t)(2 * vpp) * C3 + vn0;
        va = *reinterpret_cast<const uint4*>(vp);
        vb = *reinterpret_cast<const uint4*>(vp + C3);
        const uint32_t* kw0 = reinterpret_cast<const uint32_t*>(&ku0);
        const uint32_t* kw1 = reinterpret_cast<const uint32_t*>(&ku1);
        const uint32_t* vwa = reinterpret_cast<const uint32_t*>(&va);
        const uint32_t* vwb = reinterpret_cast<const uint32_t*>(&vb);
#pragma unroll
        for (int i = 0; i < 4; i++) {
            sK[0][kb + i * 2]     = kw0[i];
            sK[0][kb + i * 2 + 1] = kw1[i];
            sV[0][vst[i]]     = __byte_perm(vwa[i], vwb[i], 0x5410);
            sV[0][vst[i] + 8] = __byte_perm(vwa[i], vwb[i], 0x7632);
        }
    }
    __syncthreads();

    for (int kt = 0; kt < 16; kt++) {
        const int s = kt & 1;
        if (kt + 1 < 16) {
            const __half* kp = kbase + (size_t)((kt + 1) * 64 + knr) * C3 + kq * 16;
            ku0 = *reinterpret_cast<const uint4*>(kp);
            ku1 = *reinterpret_cast<const uint4*>(kp + 8);
            const __half* vp = vbase + (size_t)((kt + 1) * 64 + 2 * vpp) * C3 + vn0;
            va = *reinterpret_cast<const uint4*>(vp);
            vb = *reinterpret_cast<const uint4*>(vp + C3);
        }

        float sacc[8][4];
#pragma unroll
        for (int nt = 0; nt < 8; nt++) {
#pragma unroll
            for (int i = 0; i < 4; i++) sacc[nt][i] = 0.f;
#pragma unroll
            for (int ks = 0; ks < 4; ks++) {
                uint32_t bfr[2];
                *reinterpret_cast<uint2*>(bfr) =
                    *reinterpret_cast<const uint2*>(&sK[s][ks * 512 + nt * 64 + lane * 2]);
                mma_f16(sacc[nt], af[ks], bfr);
            }
        }

        float m0 = -1e30f, m1 = -1e30f;
#pragma unroll
        for (int nt = 0; nt < 8; nt++) {
#pragma unroll
            for (int i = 0; i < 4; i++) sacc[nt][i] *= 0.125f;
            m0 = fmaxf(m0, fmaxf(sacc[nt][0], sacc[nt][1]));
            m1 = fmaxf(m1, fmaxf(sacc[nt][2], sacc[nt][3]));
        }
        m0 = fmaxf(m0, __shfl_xor_sync(0xffffffffu, m0, 1));
        m0 = fmaxf(m0, __shfl_xor_sync(0xffffffffu, m0, 2));
        m1 = fmaxf(m1, __shfl_xor_sync(0xffffffffu, m1, 1));
        m1 = fmaxf(m1, __shfl_xor_sync(0xffffffffu, m1, 2));
        const float mn0 = fmaxf(mrun0, m0), mn1 = fmaxf(mrun1, m1);
        const float al0 = __expf(mrun0 - mn0), al1 = __expf(mrun1 - mn1);
        mrun0 = mn0; mrun1 = mn1;

        float r0 = 0.f, r1 = 0.f;
#pragma unroll
        for (int nt = 0; nt < 8; nt++) {
            sacc[nt][0] = __expf(sacc[nt][0] - mn0);
            sacc[nt][1] = __expf(sacc[nt][1] - mn0);
            sacc[nt][2] = __expf(sacc[nt][2] - mn1);
            sacc[nt][3] = __expf(sacc[nt][3] - mn1);
            r0 += sacc[nt][0] + sacc[nt][1];
            r1 += sacc[nt][2] + sacc[nt][3];
        }
        r0 += __shfl_xor_sync(0xffffffffu, r0, 1);
        r0 += __shfl_xor_sync(0xffffffffu, r0, 2);
        r1 += __shfl_xor_sync(0xffffffffu, r1, 1);
        r1 += __shfl_xor_sync(0xffffffffu, r1, 2);
        lrun0 = lrun0 * al0 + r0;
        lrun1 = lrun1 * al1 + r1;

#pragma unroll
        for (int nt = 0; nt < 8; nt++) {
            oacc[nt][0] *= al0; oacc[nt][1] *= al0;
            oacc[nt][2] *= al1; oacc[nt][3] *= al1;
        }

        uint32_t pf[4][4];
#pragma unroll
        for (int ks = 0; ks < 4; ks++) {
            pf[ks][0] = h2pack(sacc[2 * ks][0],     sacc[2 * ks][1]);
            pf[ks][1] = h2pack(sacc[2 * ks][2],     sacc[2 * ks][3]);
            pf[ks][2] = h2pack(sacc[2 * ks + 1][0], sacc[2 * ks + 1][1]);
            pf[ks][3] = h2pack(sacc[2 * ks + 1][2], sacc[2 * ks + 1][3]);
        }
#pragma unroll
        for (int nt = 0; nt < 8; nt++) {
#pragma unroll
            for (int ks = 0; ks < 4; ks++) {
                uint32_t bfr[2];
                *reinterpret_cast<uint2*>(bfr) =
                    *reinterpret_cast<const uint2*>(&sV[s][ks * 512 + nt * 64 + lane * 2]);
                mma_f16(oacc[nt], pf[ks], bfr);
            }
        }

        if (kt + 1 < 16) {
            const int ns = s ^ 1;
            const uint32_t* kw0 = reinterpret_cast<const uint32_t*>(&ku0);
            const uint32_t* kw1 = reinterpret_cast<const uint32_t*>(&ku1);
            const uint32_t* vwa = reinterpret_cast<const uint32_t*>(&va);
            const uint32_t* vwb = reinterpret_cast<const uint32_t*>(&vb);
#pragma unroll
            for (int i = 0; i < 4; i++) {
                sK[ns][kb + i * 2]     = kw0[i];
                sK[ns][kb + i * 2 + 1] = kw1[i];
                sV[ns][vst[i]]     = __byte_perm(vwa[i], vwb[i], 0x5410);
                sV[ns][vst[i] + 8] = __byte_perm(vwa[i], vwb[i], 0x7632);
            }
        }
        __syncthreads();
    }

    const float inv0 = 1.f / lrun0, inv1 = 1.f / lrun1;
    const int rowA = b * NT + qt * 128 + warp * 16 + (lane >> 2);
    const int colb = h * NHD + (lane & 3) * 2;
#pragma unroll
    for (int nt = 0; nt < 8; nt++) {
        yt[a_widx(rowA,     colb + nt * 8, 64)] =
            h2pack(oacc[nt][0] * inv0, oacc[nt][1] * inv0);
        yt[a_widx(rowA + 8, colb + nt * 8, 64)] =
            h2pack(oacc[nt][2] * inv1, oacc[nt][3] * inv1);
    }
}

// ---------------- host orchestration -----------------------------------------
#define SMEM_W   65536
#define SMEM_T64 49152

extern "C" void kernel_launch(void* const* d_in, const int* in_sizes, int n_in,
                              void* d_out, int out_size) {
    const int*   ids    = (const int*)  d_in[0];
    const float* wte    = (const float*)d_in[1];
    const float* wpe    = (const float*)d_in[2];
    const float* ln1_w  = (const float*)d_in[3];
    const float* ln1_b  = (const float*)d_in[4];
    const float* attn_w = (const float*)d_in[5];
    const float* attn_b = (const float*)d_in[6];
    const float* proj_w = (const float*)d_in[7];
    const float* proj_b = (const float*)d_in[8];
    const float* ln2_w  = (const float*)d_in[9];
    const float* ln2_b  = (const float*)d_in[10];
    const float* fc_w   = (const float*)d_in[11];
    const float* fc_b   = (const float*)d_in[12];
    const float* fc2_w  = (const float*)d_in[13];
    const float* fc2_b  = (const float*)d_in[14];
    const float* lnf_w  = (const float*)d_in[15];
    const float* lnf_b  = (const float*)d_in[16];
    float* out = (float*)d_out;

    float* x;
    __half* qkv16;
    uint32_t *h16t, *y16t, *mlp16t, *wa, *wp, *wf, *wf2, *wv;
    cudaGetSymbolAddress((void**)&x,      g_x);
    cudaGetSymbolAddress((void**)&qkv16,  g_qkv16);
    cudaGetSymbolAddress((void**)&h16t,   g_h16t);
    cudaGetSymbolAddress((void**)&y16t,   g_y16t);
    cudaGetSymbolAddress((void**)&mlp16t, g_mlp16t);
    cudaGetSymbolAddress((void**)&wa,     w_attn_t);
    cudaGetSymbolAddress((void**)&wp,     w_proj_t);
    cudaGetSymbolAddress((void**)&wf,     w_fc_t);
    cudaGetSymbolAddress((void**)&wf2,    w_fc2_t);
    cudaGetSymbolAddress((void**)&wv,     w_wte_t);

    cudaFuncSetAttribute((const void*)hgemm_w<2, 2>, cudaFuncAttributeMaxDynamicSharedMemorySize, SMEM_W);
    cudaFuncSetAttribute((const void*)hgemm_w<3, 3>, cudaFuncAttributeMaxDynamicSharedMemorySize, SMEM_W);
    cudaFuncSetAttribute((const void*)hgemm_w<4, 3>, cudaFuncAttributeMaxDynamicSharedMemorySize, SMEM_W);
    cudaFuncSetAttribute((const void*)hgemm_t64,     cudaFuncAttributeMaxDynamicSharedMemorySize, SMEM_T64);

    embed_kernel<<<NTOK, 256>>>(ids, wte, wpe, x);
    cvt_all<<<74304, 256>>>(attn_w, proj_w, fc_w, fc2_w, wte, wa, wp, wf, wf2, wv);

    const size_t wa_s = (size_t)NC * C3 / 2, wp_s = (size_t)NC * NC / 2;
    const size_t wf_s = (size_t)NC * C4 / 2, wf2_s = (size_t)C4 * NC / 2;

    for (int l = 0; l < NL; l++) {
        ln_kernel<<<NTOK, 256>>>(x, ln1_w + (size_t)l * NC, ln1_b + (size_t)l * NC, h16t);
        hgemm_w<3, 3><<<dim3(C3 / 128, NTOK / 128), 128, SMEM_W>>>(
            h16t, wa + l * wa_s, attn_b + (size_t)l * C3, qkv16, C3, 64);
        flash_attn<<<dim3(NT / 128, NB * NH), 256>>>(qkv16, y16t);
        hgemm_t64<<<dim3(NC / 128, NTOK / 64), 256, SMEM_T64>>>(
            y16t, wp + l * wp_s, proj_b + (size_t)l * NC, x, NC, 64);
        ln_kernel<<<NTOK, 256>>>(x, ln2_w + (size_t)l * NC, ln2_b + (size_t)l * NC, h16t);
        hgemm_w<2, 2><<<dim3(C4 / 128, NTOK / 128), 128, SMEM_W>>>(
            h16t, wf + l * wf_s, fc_b + (size_t)l * C4, mlp16t, C4, 64);
        hgemm_t64<<<dim3(NC / 128, NTOK / 64), 256, SMEM_T64>>>(
            mlp16t, wf2 + l * wf2_s, fc2_b + (size_t)l * NC, x, NC, 256);
    }

    ln_kernel<<<NTOK, 256>>>(x, lnf_w, lnf_b, h16t);
    hgemm_w<4, 3><<<dim3(NVP / 128, NTOK / 128), 128, SMEM_W>>>(
        h16t, wv, nullptr, out, NV, 64);
}